// round 8
// baseline (speedup 1.0000x reference)
#include <cuda_runtime.h>
#include <math.h>
#include <cstdint>

#define B_   4
#define LQ_  2048
#define LK_  2048
#define IND  1024
#define NH_  16
#define HD_  64
#define HDA  1024
#define NZ   (B_*NH_)
#define NEGV (-1e9f)

typedef unsigned long long u64;

// Scratch (device globals — no allocation allowed)
__device__ float  g_Qh[(size_t)NZ * HD_ * LQ_];   // [z][d][q]  (transposed, pre-scaled)
__device__ float  g_Kh[(size_t)NZ * HD_ * LK_];   // [z][d][k]  (transposed)
__device__ float  g_Vh[(size_t)NZ * LK_ * HD_];   // [z][k][d]
__device__ float  g_Oh[(size_t)B_ * LQ_ * HDA];   // [b][q][h*d]
__device__ float2 g_part[(size_t)NZ * 16 * LQ_];  // per-(z, n-tile, row) {max, expsum}
__device__ float2 g_stats[(size_t)NZ * LQ_];      // {rowmax, 1/rowsum}

// ---------------- packed f32x2 helpers ----------------
__device__ __forceinline__ u64 pack2(float x, float y) {
    u64 r;
    asm("mov.b64 %0, {%1, %2};" : "=l"(r) : "f"(x), "f"(y));
    return r;
}
__device__ __forceinline__ float2 unpack2(u64 v) {
    float x, y;
    asm("mov.b64 {%0, %1}, %2;" : "=f"(x), "=f"(y) : "l"(v));
    return make_float2(x, y);
}
__device__ __forceinline__ u64 ffma2(u64 a, u64 b, u64 c) {
    u64 d;
    asm("fma.rn.f32x2 %0, %1, %2, %3;" : "=l"(d) : "l"(a), "l"(b), "l"(c));
    return d;
}

// ---------------------------------------------------------------------------
// Projection GEMM: Y = alpha*(X @ W^T + bias). CTA tile 256(M)x128(N), BK=16,
// 256 threads, 16x8 microtile via f32x2.
// transposed=1 -> Y[z][d][l], else Y[z][l][d].
// ---------------------------------------------------------------------------
__global__ __launch_bounds__(256) void proj_kernel(
    const float* __restrict__ X, const float* __restrict__ W,
    const float* __restrict__ bias, float* __restrict__ Y,
    float alpha, int transposed)
{
    const int bm = blockIdx.y * 256;
    const int bn = blockIdx.x * 128;
    __shared__ __align__(16) float As[16][260];
    __shared__ __align__(16) float Bs[16][132];
    const int t  = threadIdx.x;
    const int tx = t & 15, ty = t >> 4;       // compute: 16 tx x 16 ty
    const int br = t >> 1, bh = t & 1;        // B loader: row, col-octet

    u64 acc2[16][4];
    #pragma unroll
    for (int i = 0; i < 16; i++)
        #pragma unroll
        for (int j = 0; j < 4; j++) acc2[i][j] = pack2(0.f, 0.f);

    const float* Ap = X + (size_t)(bm + t) * IND;
    const float* Bp = W + (size_t)(bn + br) * IND + bh * 8;

    for (int kt = 0; kt < IND; kt += 16) {
        // A: one row per thread, 16 floats
        {
            float4 v0 = *(const float4*)(Ap + kt);
            float4 v1 = *(const float4*)(Ap + kt + 4);
            float4 v2 = *(const float4*)(Ap + kt + 8);
            float4 v3 = *(const float4*)(Ap + kt + 12);
            As[0][t]=v0.x;  As[1][t]=v0.y;  As[2][t]=v0.z;  As[3][t]=v0.w;
            As[4][t]=v1.x;  As[5][t]=v1.y;  As[6][t]=v1.z;  As[7][t]=v1.w;
            As[8][t]=v2.x;  As[9][t]=v2.y;  As[10][t]=v2.z; As[11][t]=v2.w;
            As[12][t]=v3.x; As[13][t]=v3.y; As[14][t]=v3.z; As[15][t]=v3.w;
        }
        // B: two threads per row, 8 floats each
        {
            float4 v0 = *(const float4*)(Bp + kt);
            float4 v1 = *(const float4*)(Bp + kt + 4);
            const int c = bh * 8;
            Bs[c+0][br]=v0.x; Bs[c+1][br]=v0.y; Bs[c+2][br]=v0.z; Bs[c+3][br]=v0.w;
            Bs[c+4][br]=v1.x; Bs[c+5][br]=v1.y; Bs[c+6][br]=v1.z; Bs[c+7][br]=v1.w;
        }
        __syncthreads();
        #pragma unroll
        for (int kk = 0; kk < 16; kk++) {
            const u64* bp2 = (const u64*)&Bs[kk][tx * 8];
            u64 b2[4] = {bp2[0], bp2[1], bp2[2], bp2[3]};
            float4 x0 = *(const float4*)&As[kk][ty * 16];
            float4 x1 = *(const float4*)&As[kk][ty * 16 + 4];
            float4 x2 = *(const float4*)&As[kk][ty * 16 + 8];
            float4 x3 = *(const float4*)&As[kk][ty * 16 + 12];
            float a[16] = {x0.x,x0.y,x0.z,x0.w,x1.x,x1.y,x1.z,x1.w,
                           x2.x,x2.y,x2.z,x2.w,x3.x,x3.y,x3.z,x3.w};
            #pragma unroll
            for (int i = 0; i < 16; i++) {
                const u64 a2 = pack2(a[i], a[i]);
                #pragma unroll
                for (int j = 0; j < 4; j++)
                    acc2[i][j] = ffma2(a2, b2[j], acc2[i][j]);
            }
        }
        __syncthreads();
    }

    if (!transposed) {
        #pragma unroll
        for (int i = 0; i < 16; i++) {
            const int m  = bm + ty * 16 + i;
            const int bb = m >> 11, l = m & 2047;
            const int n0 = bn + tx * 8;
            const int h  = n0 >> 6, dd = n0 & 63;
            float* dst = Y + (((size_t)(bb * NH_ + h) * LK_) + l) * HD_ + dd;
            float2 p0 = unpack2(acc2[i][0]), p1 = unpack2(acc2[i][1]);
            float2 p2 = unpack2(acc2[i][2]), p3 = unpack2(acc2[i][3]);
            float4 o0, o1;
            o0.x = alpha * (p0.x + bias[n0+0]);
            o0.y = alpha * (p0.y + bias[n0+1]);
            o0.z = alpha * (p1.x + bias[n0+2]);
            o0.w = alpha * (p1.y + bias[n0+3]);
            o1.x = alpha * (p2.x + bias[n0+4]);
            o1.y = alpha * (p2.y + bias[n0+5]);
            o1.z = alpha * (p3.x + bias[n0+6]);
            o1.w = alpha * (p3.y + bias[n0+7]);
            *(float4*)(dst)     = o0;
            *(float4*)(dst + 4) = o1;
        }
    } else {
        const int m0 = bm + ty * 16;
        const int bb = m0 >> 11, l0 = m0 & 2047;
        #pragma unroll
        for (int jp = 0; jp < 4; jp++) {
            float c0[16], c1[16];
            #pragma unroll
            for (int i = 0; i < 16; i++) {
                float2 p = unpack2(acc2[i][jp]);
                c0[i] = p.x; c1[i] = p.y;
            }
            #pragma unroll
            for (int s = 0; s < 2; s++) {
                const float* cc = s ? c1 : c0;
                const int n = bn + tx * 8 + jp * 2 + s;
                const int h = n >> 6, dd = n & 63;
                float* dst = Y + (((size_t)(bb * NH_ + h) * HD_) + dd) * LQ_ + l0;
                const float bi = bias[n];
                #pragma unroll
                for (int q4 = 0; q4 < 4; q4++) {
                    float4 o;
                    o.x = alpha * (cc[q4*4+0] + bi);
                    o.y = alpha * (cc[q4*4+1] + bi);
                    o.z = alpha * (cc[q4*4+2] + bi);
                    o.w = alpha * (cc[q4*4+3] + bi);
                    *(float4*)(dst + q4 * 4) = o;
                }
            }
        }
    }
}

// ---------------------------------------------------------------------------
// QK^T: CTA tile 256(M)x128(N), BK=16 (d-major operands), 16x8 microtile.
// Epilogue: mask -> NEGV, raw logits + per-(n-tile,row) softmax partials.
// ---------------------------------------------------------------------------
__global__ __launch_bounds__(256) void qk_kernel(
    const int* __restrict__ mask, float* __restrict__ S)
{
    const int z  = blockIdx.z;
    const int bm = blockIdx.y * 256;
    const int bn = blockIdx.x * 128;
    const float* Q = g_Qh + (size_t)z * HD_ * LQ_;
    const float* K = g_Kh + (size_t)z * HD_ * LK_;

    __shared__ __align__(16) float As[16][260];
    __shared__ __align__(16) float Bs[16][132];
    const int t  = threadIdx.x;
    const int tx = t & 15, ty = t >> 4;
    const int dr = t >> 4, g = t & 15;

    u64 acc2[16][4];
    #pragma unroll
    for (int i = 0; i < 16; i++)
        #pragma unroll
        for (int j = 0; j < 4; j++) acc2[i][j] = pack2(0.f, 0.f);

    for (int kt = 0; kt < HD_; kt += 16) {
        // A: 16 d-rows x 256 m; thread (dr, g) loads 16 floats
        {
            const float* qp = Q + (size_t)(kt + dr) * LQ_ + bm + g * 16;
            *(float4*)&As[dr][g * 16]      = *(const float4*)(qp);
            *(float4*)&As[dr][g * 16 + 4]  = *(const float4*)(qp + 4);
            *(float4*)&As[dr][g * 16 + 8]  = *(const float4*)(qp + 8);
            *(float4*)&As[dr][g * 16 + 12] = *(const float4*)(qp + 12);
        }
        // B: 16 d-rows x 128 n; thread (dr, g) loads 8 floats
        {
            const float* kp = K + (size_t)(kt + dr) * LK_ + bn + g * 8;
            *(float4*)&Bs[dr][g * 8]     = *(const float4*)(kp);
            *(float4*)&Bs[dr][g * 8 + 4] = *(const float4*)(kp + 4);
        }
        __syncthreads();
        #pragma unroll
        for (int kk = 0; kk < 16; kk++) {
            const u64* bp2 = (const u64*)&Bs[kk][tx * 8];
            u64 b2[4] = {bp2[0], bp2[1], bp2[2], bp2[3]};
            float4 x0 = *(const float4*)&As[kk][ty * 16];
            float4 x1 = *(const float4*)&As[kk][ty * 16 + 4];
            float4 x2 = *(const float4*)&As[kk][ty * 16 + 8];
            float4 x3 = *(const float4*)&As[kk][ty * 16 + 12];
            float a[16] = {x0.x,x0.y,x0.z,x0.w,x1.x,x1.y,x1.z,x1.w,
                           x2.x,x2.y,x2.z,x2.w,x3.x,x3.y,x3.z,x3.w};
            #pragma unroll
            for (int i = 0; i < 16; i++) {
                const u64 a2 = pack2(a[i], a[i]);
                #pragma unroll
                for (int j = 0; j < 4; j++)
                    acc2[i][j] = ffma2(a2, b2[j], acc2[i][j]);
            }
        }
        __syncthreads();
    }

    // Epilogue: mask, write raw logits, per-(n-tile) partial stats
    float* Sz = S + (size_t)z * LQ_ * LK_;
    float2* part = g_part + ((size_t)z * 16 + blockIdx.x) * LQ_;
    #pragma unroll
    for (int i = 0; i < 16; i++) {
        const int m  = bm + ty * 16 + i;
        const int n0 = bn + tx * 8;
        float v[8];
        {
            float2 p0 = unpack2(acc2[i][0]), p1 = unpack2(acc2[i][1]);
            float2 p2 = unpack2(acc2[i][2]), p3 = unpack2(acc2[i][3]);
            v[0]=p0.x; v[1]=p0.y; v[2]=p1.x; v[3]=p1.y;
            v[4]=p2.x; v[5]=p2.y; v[6]=p3.x; v[7]=p3.y;
        }
        const int4 m0 = *(const int4*)&mask[(size_t)m * LK_ + n0];
        const int4 m1 = *(const int4*)&mask[(size_t)m * LK_ + n0 + 4];
        v[0] = m0.x ? v[0] : NEGV;
        v[1] = m0.y ? v[1] : NEGV;
        v[2] = m0.z ? v[2] : NEGV;
        v[3] = m0.w ? v[3] : NEGV;
        v[4] = m1.x ? v[4] : NEGV;
        v[5] = m1.y ? v[5] : NEGV;
        v[6] = m1.z ? v[6] : NEGV;
        v[7] = m1.w ? v[7] : NEGV;

        float mx = v[0];
        #pragma unroll
        for (int j = 1; j < 8; j++) mx = fmaxf(mx, v[j]);
        #pragma unroll
        for (int o = 8; o > 0; o >>= 1)
            mx = fmaxf(mx, __shfl_xor_sync(0xffffffffu, mx, o));
        float s = 0.f;
        #pragma unroll
        for (int j = 0; j < 8; j++) s += __expf(v[j] - mx);
        #pragma unroll
        for (int o = 8; o > 0; o >>= 1)
            s += __shfl_xor_sync(0xffffffffu, s, o);

        *(float4*)&Sz[(size_t)m * LK_ + n0]     = make_float4(v[0], v[1], v[2], v[3]);
        *(float4*)&Sz[(size_t)m * LK_ + n0 + 4] = make_float4(v[4], v[5], v[6], v[7]);
        if (tx == 0) part[m] = make_float2(mx, s);
    }
}

// ---------------------------------------------------------------------------
// Combine 16 partial stats per row -> {rowmax, 1/rowsum}.
// ---------------------------------------------------------------------------
__global__ __launch_bounds__(256) void combine_kernel()
{
    const int idx = blockIdx.x * 256 + threadIdx.x;
    if (idx >= NZ * LQ_) return;
    const int z = idx >> 11, m = idx & 2047;
    const float2* p = g_part + (size_t)z * 16 * LQ_ + m;
    float M = -3.4e38f;
    #pragma unroll
    for (int i = 0; i < 16; i++) M = fmaxf(M, p[(size_t)i * LQ_].x);
    float Ssum = 0.f;
    #pragma unroll
    for (int i = 0; i < 16; i++) {
        const float2 q = p[(size_t)i * LQ_];
        Ssum += q.y * __expf(q.x - M);
    }
    g_stats[idx] = make_float2(M, 1.0f / Ssum);
}

// ---------------------------------------------------------------------------
// PV fused with normalization. CTA tile 256(M)x64(N), BK=16, 8x8 microtile.
// Reads raw logits, p = exp(s-max)/sum, writes final probs back, O = P @ V.
// ---------------------------------------------------------------------------
__global__ __launch_bounds__(256) void pv_kernel(float* __restrict__ S)
{
    const int z  = blockIdx.y;
    const int bm = blockIdx.x * 256;
    const float* V = g_Vh + (size_t)z * LK_ * HD_;
    float* Sz = S + (size_t)z * LQ_ * LK_;

    __shared__ __align__(16) float Ps[16][260];
    __shared__ __align__(16) float Vs[16][68];
    const int t  = threadIdx.x;
    const int tx = t & 7, ty = t >> 3;        // compute: 8 tx x 32 ty
    const int vk = t >> 4, vg = t & 15;       // V loader

    const float2 st = g_stats[(size_t)z * LQ_ + bm + t];
    float* Sr = Sz + (size_t)(bm + t) * LK_;

    u64 acc2[8][4];
    #pragma unroll
    for (int i = 0; i < 8; i++)
        #pragma unroll
        for (int j = 0; j < 4; j++) acc2[i][j] = pack2(0.f, 0.f);

    for (int kt = 0; kt < LK_; kt += 16) {
        // S: one row per thread, 16 floats: normalize, write back, stage
        {
            float4 s0 = *(const float4*)(Sr + kt);
            float4 s1 = *(const float4*)(Sr + kt + 4);
            float4 s2 = *(const float4*)(Sr + kt + 8);
            float4 s3 = *(const float4*)(Sr + kt + 12);
            s0.x = __expf(s0.x - st.x) * st.y;
            s0.y = __expf(s0.y - st.x) * st.y;
            s0.z = __expf(s0.z - st.x) * st.y;
            s0.w = __expf(s0.w - st.x) * st.y;
            s1.x = __expf(s1.x - st.x) * st.y;
            s1.y = __expf(s1.y - st.x) * st.y;
            s1.z = __expf(s1.z - st.x) * st.y;
            s1.w = __expf(s1.w - st.x) * st.y;
            s2.x = __expf(s2.x - st.x) * st.y;
            s2.y = __expf(s2.y - st.x) * st.y;
            s2.z = __expf(s2.z - st.x) * st.y;
            s2.w = __expf(s2.w - st.x) * st.y;
            s3.x = __expf(s3.x - st.x) * st.y;
            s3.y = __expf(s3.y - st.x) * st.y;
            s3.z = __expf(s3.z - st.x) * st.y;
            s3.w = __expf(s3.w - st.x) * st.y;
            *(float4*)(Sr + kt)      = s0;
            *(float4*)(Sr + kt + 4)  = s1;
            *(float4*)(Sr + kt + 8)  = s2;
            *(float4*)(Sr + kt + 12) = s3;
            Ps[0][t]=s0.x;  Ps[1][t]=s0.y;  Ps[2][t]=s0.z;  Ps[3][t]=s0.w;
            Ps[4][t]=s1.x;  Ps[5][t]=s1.y;  Ps[6][t]=s1.z;  Ps[7][t]=s1.w;
            Ps[8][t]=s2.x;  Ps[9][t]=s2.y;  Ps[10][t]=s2.z; Ps[11][t]=s2.w;
            Ps[12][t]=s3.x; Ps[13][t]=s3.y; Ps[14][t]=s3.z; Ps[15][t]=s3.w;
        }
        // V chunk 16x64
        *(float4*)&Vs[vk][vg * 4] = *(const float4*)&V[(size_t)(kt + vk) * HD_ + vg * 4];
        __syncthreads();
        #pragma unroll
        for (int kk = 0; kk < 16; kk++) {
            const u64* bp2 = (const u64*)&Vs[kk][tx * 8];
            u64 b2[4] = {bp2[0], bp2[1], bp2[2], bp2[3]};
            float4 x0 = *(const float4*)&Ps[kk][ty * 8];
            float4 x1 = *(const float4*)&Ps[kk][ty * 8 + 4];
            float a[8] = {x0.x,x0.y,x0.z,x0.w,x1.x,x1.y,x1.z,x1.w};
            #pragma unroll
            for (int i = 0; i < 8; i++) {
                const u64 a2 = pack2(a[i], a[i]);
                #pragma unroll
                for (int j = 0; j < 4; j++)
                    acc2[i][j] = ffma2(a2, b2[j], acc2[i][j]);
            }
        }
        __syncthreads();
    }

    const int bb = z >> 4, h = z & 15;
    #pragma unroll
    for (int i = 0; i < 8; i++) {
        const int q = bm + ty * 8 + i;
        float2 p0 = unpack2(acc2[i][0]), p1 = unpack2(acc2[i][1]);
        float2 p2 = unpack2(acc2[i][2]), p3 = unpack2(acc2[i][3]);
        float* dst = &g_Oh[((size_t)bb * LQ_ + q) * HDA + h * HD_ + tx * 8];
        *(float4*)(dst)     = make_float4(p0.x, p0.y, p1.x, p1.y);
        *(float4*)(dst + 4) = make_float4(p2.x, p2.y, p3.x, p3.y);
    }
}

// ---------------------------------------------------------------------------
// Output GEMM: out = Oh @ wo^T + bo, M=8192, N=64, K=1024. f32x2.
// ---------------------------------------------------------------------------
__global__ __launch_bounds__(256) void o_kernel(
    const float* __restrict__ wo, const float* __restrict__ bo,
    float* __restrict__ out)
{
    const int bm = blockIdx.x * 64;
    __shared__ float As[16][68];
    __shared__ float Ws[16][68];
    const int t  = threadIdx.x;
    const int tx = t % 16, ty = t / 16;
    const int lk = t % 16, lr = t / 16;

    u64 acc2[4][2];
    #pragma unroll
    for (int i = 0; i < 4; i++) {
        acc2[i][0] = pack2(0.f, 0.f);
        acc2[i][1] = pack2(0.f, 0.f);
    }

    for (int kt = 0; kt < HDA; kt += 16) {
        #pragma unroll
        for (int i = 0; i < 4; i++) {
            const int m = i * 16 + lr;
            As[lk][m] = g_Oh[(size_t)(bm + m) * HDA + kt + lk];
            Ws[lk][m] = wo  [(size_t)m        * HDA + kt + lk];
        }
        __syncthreads();
        #pragma unroll
        for (int kk = 0; kk < 16; kk++) {
            float a[4], b[4];
            #pragma unroll
            for (int i = 0; i < 4; i++) a[i] = As[kk][ty * 4 + i];
            #pragma unroll
            for (int j = 0; j < 4; j++) b[j] = Ws[kk][tx + 16 * j];
            const u64 b20 = pack2(b[0], b[1]);
            const u64 b21 = pack2(b[2], b[3]);
            #pragma unroll
            for (int i = 0; i < 4; i++) {
                const u64 a2 = pack2(a[i], a[i]);
                acc2[i][0] = ffma2(a2, b20, acc2[i][0]);
                acc2[i][1] = ffma2(a2, b21, acc2[i][1]);
            }
        }
        __syncthreads();
    }

    #pragma unroll
    for (int i = 0; i < 4; i++) {
        const int m = bm + ty * 4 + i;
        float2 p0 = unpack2(acc2[i][0]), p1 = unpack2(acc2[i][1]);
        out[(size_t)m * HD_ + tx]      = p0.x + bo[tx];
        out[(size_t)m * HD_ + tx + 16] = p0.y + bo[tx + 16];
        out[(size_t)m * HD_ + tx + 32] = p1.x + bo[tx + 32];
        out[(size_t)m * HD_ + tx + 48] = p1.y + bo[tx + 48];
    }
}

// ---------------------------------------------------------------------------
extern "C" void kernel_launch(void* const* d_in, const int* in_sizes, int n_in,
                              void* d_out, int out_size)
{
    (void)in_sizes; (void)n_in; (void)out_size;
    const float* q    = (const float*)d_in[0];
    const float* k    = (const float*)d_in[1];
    const float* v    = (const float*)d_in[2];
    const int*   mask = (const int*)  d_in[3];
    const float* wq   = (const float*)d_in[4];
    const float* bq   = (const float*)d_in[5];
    const float* wk   = (const float*)d_in[6];
    const float* bk   = (const float*)d_in[7];
    const float* wv   = (const float*)d_in[8];
    const float* bv   = (const float*)d_in[9];
    const float* wo   = (const float*)d_in[10];
    const float* bo   = (const float*)d_in[11];

    float* out    = (float*)d_out;                       // [B, LQ, 64]
    float* scores = out + (size_t)B_ * LQ_ * HD_;        // [B, H, LQ, LK]

    float *Qh, *Kh, *Vh;
    cudaGetSymbolAddress((void**)&Qh, g_Qh);
    cudaGetSymbolAddress((void**)&Kh, g_Kh);
    cudaGetSymbolAddress((void**)&Vh, g_Vh);

    const dim3 blk(256);
    const dim3 gproj(IND / 128, (B_ * LQ_) / 256);       // (8, 32)
    proj_kernel<<<gproj, blk>>>(q, wq, bq, Qh, 0.125f, 1);  // -> [z][d][q]
    proj_kernel<<<gproj, blk>>>(k, wk, bk, Kh, 1.0f,   1);  // -> [z][d][k]
    proj_kernel<<<gproj, blk>>>(v, wv, bv, Vh, 1.0f,   0);  // -> [z][k][d]

    const dim3 gqk(LK_ / 128, LQ_ / 256, NZ);            // (16, 8, 64)
    qk_kernel<<<gqk, blk>>>(mask, scores);

    combine_kernel<<<(NZ * LQ_ + 255) / 256, blk>>>();   // 512 blocks

    const dim3 gpv(LQ_ / 256, NZ);                       // (8, 64)
    pv_kernel<<<gpv, blk>>>(scores);

    o_kernel<<<(B_ * LQ_) / 64, blk>>>(wo, bo, out);     // 128 blocks
}

// round 10
// speedup vs baseline: 1.2793x; 1.2793x over previous
#include <cuda_runtime.h>
#include <cuda_bf16.h>
#include <math.h>
#include <cstdint>

#define B_   4
#define LQ_  2048
#define LK_  2048
#define IND  1024
#define NH_  16
#define HD_  64
#define HDA  1024
#define NZ   (B_*NH_)
#define NEGV (-1e9f)

typedef unsigned long long u64;

// Scratch (device globals)
__device__ __nv_bfloat16 g_Qhi[(size_t)NZ * LQ_ * HD_];  // [z][l][d]
__device__ __nv_bfloat16 g_Qlo[(size_t)NZ * LQ_ * HD_];
__device__ __nv_bfloat16 g_Khi[(size_t)NZ * LK_ * HD_];
__device__ __nv_bfloat16 g_Klo[(size_t)NZ * LK_ * HD_];
__device__ float  g_Vh[(size_t)NZ * LK_ * HD_];          // [z][k][d]
__device__ float  g_Oh[(size_t)B_ * LQ_ * HDA];          // [b][q][h*d]
__device__ float2 g_part[(size_t)NZ * 64 * LQ_];         // per-(z, 32col-tile, row)
__device__ float2 g_stats[(size_t)NZ * LQ_];             // {rowmax, 1/rowsum}

// ---------------- helpers ----------------
__device__ __forceinline__ u64 pack2(float x, float y) {
    u64 r; asm("mov.b64 %0, {%1, %2};" : "=l"(r) : "f"(x), "f"(y)); return r;
}
__device__ __forceinline__ float2 unpack2(u64 v) {
    float x, y; asm("mov.b64 {%0, %1}, %2;" : "=f"(x), "=f"(y) : "l"(v));
    return make_float2(x, y);
}
__device__ __forceinline__ u64 ffma2(u64 a, u64 b, u64 c) {
    u64 d; asm("fma.rn.f32x2 %0, %1, %2, %3;" : "=l"(d) : "l"(a), "l"(b), "l"(c));
    return d;
}
__device__ __forceinline__ uint32_t smem_u32(const void* p) {
    uint32_t a;
    asm("{ .reg .u64 t; cvta.to.shared.u64 t, %1; cvt.u32.u64 %0, t; }" : "=r"(a) : "l"(p));
    return a;
}
__device__ __forceinline__ void cpa16(uint32_t dst, const void* src) {
    asm volatile("cp.async.cg.shared.global [%0], [%1], 16;" :: "r"(dst), "l"(src));
}
#define CP_COMMIT() asm volatile("cp.async.commit_group;" ::: "memory")
#define CP_WAIT0()  asm volatile("cp.async.wait_group 0;" ::: "memory")

__device__ __forceinline__ void ldsm4(uint32_t (&r)[4], uint32_t addr) {
    asm volatile("ldmatrix.sync.aligned.m8n8.x4.shared.b16 {%0,%1,%2,%3}, [%4];"
                 : "=r"(r[0]), "=r"(r[1]), "=r"(r[2]), "=r"(r[3]) : "r"(addr));
}
// fragment address in a [rows][72] halves tile (144B row stride, 16B-aligned, conflict-free)
__device__ __forceinline__ uint32_t fa72(uint32_t base, int row0, int k0, int lane) {
    const int g = lane >> 3;
    const int row = row0 + (lane & 7) + ((g & 1) << 3);
    const int col = k0 + ((g >> 1) << 3);
    return base + (uint32_t)(row * 72 + col) * 2;
}
__device__ __forceinline__ void mma16816(float (&d)[4], const uint32_t (&a)[4],
                                         uint32_t b0, uint32_t b1) {
    asm volatile(
        "mma.sync.aligned.m16n8k16.row.col.f32.bf16.bf16.f32 "
        "{%0,%1,%2,%3},{%4,%5,%6,%7},{%8,%9},{%0,%1,%2,%3};"
        : "+f"(d[0]), "+f"(d[1]), "+f"(d[2]), "+f"(d[3])
        : "r"(a[0]), "r"(a[1]), "r"(a[2]), "r"(a[3]), "r"(b0), "r"(b1));
}
__device__ __forceinline__ void split8(const float* v, uint4& hi, uint4& lo) {
    unsigned short h[8], l[8];
    #pragma unroll
    for (int i = 0; i < 8; i++) {
        __nv_bfloat16 hb = __float2bfloat16_rn(v[i]);
        __nv_bfloat16 lb = __float2bfloat16_rn(v[i] - __bfloat162float(hb));
        h[i] = __bfloat16_as_ushort(hb);
        l[i] = __bfloat16_as_ushort(lb);
    }
    hi.x = h[0] | ((uint32_t)h[1] << 16); hi.y = h[2] | ((uint32_t)h[3] << 16);
    hi.z = h[4] | ((uint32_t)h[5] << 16); hi.w = h[6] | ((uint32_t)h[7] << 16);
    lo.x = l[0] | ((uint32_t)l[1] << 16); lo.y = l[2] | ((uint32_t)l[3] << 16);
    lo.z = l[4] | ((uint32_t)l[5] << 16); lo.w = l[6] | ((uint32_t)l[7] << 16);
}

// ---------------------------------------------------------------------------
// Projection GEMM (fp32 f32x2, round-7 config): Y = alpha*(X@W^T + bias).
// 128x128x16 tile, 256 threads, 8x8 microtile.
// mode 0: fp32 [z][l][d] (V). mode 1: bf16 hi/lo split [z][l][d] (Q/K).
// ---------------------------------------------------------------------------
__global__ __launch_bounds__(256) void proj_kernel(
    const float* __restrict__ X, const float* __restrict__ W,
    const float* __restrict__ bias, float alpha, int mode,
    float* __restrict__ dstF,
    __nv_bfloat16* __restrict__ dstHi, __nv_bfloat16* __restrict__ dstLo)
{
    const int bm = blockIdx.y * 128;
    const int bn = blockIdx.x * 128;
    __shared__ float As[16][132];
    __shared__ float Bs[16][132];
    const int t  = threadIdx.x;
    const int tx = t & 15, ty = t >> 4;
    const int r  = t >> 1, half = t & 1;

    const float* Ap = X + (size_t)(bm + r) * IND + half * 8;
    const float* Bp = W + (size_t)(bn + r) * IND + half * 8;

    float4 a0 = *(const float4*)(Ap);
    float4 a1 = *(const float4*)(Ap + 4);
    float4 b0 = *(const float4*)(Bp);
    float4 b1 = *(const float4*)(Bp + 4);

    u64 acc2[8][4];
    #pragma unroll
    for (int i = 0; i < 8; i++)
        #pragma unroll
        for (int j = 0; j < 4; j++) acc2[i][j] = pack2(0.f, 0.f);

    for (int kt = 0; kt < IND; kt += 16) {
        const int c = half * 8;
        As[c+0][r]=a0.x; As[c+1][r]=a0.y; As[c+2][r]=a0.z; As[c+3][r]=a0.w;
        As[c+4][r]=a1.x; As[c+5][r]=a1.y; As[c+6][r]=a1.z; As[c+7][r]=a1.w;
        Bs[c+0][r]=b0.x; Bs[c+1][r]=b0.y; Bs[c+2][r]=b0.z; Bs[c+3][r]=b0.w;
        Bs[c+4][r]=b1.x; Bs[c+5][r]=b1.y; Bs[c+6][r]=b1.z; Bs[c+7][r]=b1.w;
        __syncthreads();
        if (kt + 16 < IND) {
            a0 = *(const float4*)(Ap + kt + 16);
            a1 = *(const float4*)(Ap + kt + 20);
            b0 = *(const float4*)(Bp + kt + 16);
            b1 = *(const float4*)(Bp + kt + 20);
        }
        #pragma unroll
        for (int kk = 0; kk < 16; kk++) {
            float4 x0 = *(const float4*)&As[kk][ty * 8];
            float4 x1 = *(const float4*)&As[kk][ty * 8 + 4];
            float4 y0 = *(const float4*)&Bs[kk][tx * 8];
            float4 y1 = *(const float4*)&Bs[kk][tx * 8 + 4];
            u64 b2[4] = {pack2(y0.x, y0.y), pack2(y0.z, y0.w),
                         pack2(y1.x, y1.y), pack2(y1.z, y1.w)};
            float a[8] = {x0.x,x0.y,x0.z,x0.w,x1.x,x1.y,x1.z,x1.w};
            #pragma unroll
            for (int i = 0; i < 8; i++) {
                const u64 a2 = pack2(a[i], a[i]);
                #pragma unroll
                for (int j = 0; j < 4; j++)
                    acc2[i][j] = ffma2(a2, b2[j], acc2[i][j]);
            }
        }
        __syncthreads();
    }

    #pragma unroll
    for (int i = 0; i < 8; i++) {
        const int m  = bm + ty * 8 + i;
        const int bb = m >> 11, l = m & 2047;
        const int n0 = bn + tx * 8;
        const int h  = n0 >> 6, dd = n0 & 63;
        const size_t idx = (((size_t)(bb * NH_ + h) * LK_) + l) * HD_ + dd;
        float2 p0 = unpack2(acc2[i][0]), p1 = unpack2(acc2[i][1]);
        float2 p2 = unpack2(acc2[i][2]), p3 = unpack2(acc2[i][3]);
        float v[8];
        v[0] = alpha * (p0.x + bias[n0+0]);
        v[1] = alpha * (p0.y + bias[n0+1]);
        v[2] = alpha * (p1.x + bias[n0+2]);
        v[3] = alpha * (p1.y + bias[n0+3]);
        v[4] = alpha * (p2.x + bias[n0+4]);
        v[5] = alpha * (p2.y + bias[n0+5]);
        v[6] = alpha * (p3.x + bias[n0+6]);
        v[7] = alpha * (p3.y + bias[n0+7]);
        if (mode == 0) {
            *(float4*)&dstF[idx]     = make_float4(v[0], v[1], v[2], v[3]);
            *(float4*)&dstF[idx + 4] = make_float4(v[4], v[5], v[6], v[7]);
        } else {
            uint4 hi, lo; split8(v, hi, lo);
            *(uint4*)&dstHi[idx] = hi;
            *(uint4*)&dstLo[idx] = lo;
        }
    }
}

// ---------------------------------------------------------------------------
// QK^T via bf16x3 mma.sync: CTA 128x128, full K=64 slab in smem (cp.async),
// 512 threads = 16 warps (4m x 4n), warp tile 32x32.
// Dynamic smem: 4 tiles of [128][72] halves = 73728 B.
// Epilogue: mask -> NEGV, raw logits, per-(32col,row) softmax partials.
// ---------------------------------------------------------------------------
__global__ __launch_bounds__(512) void qk_mma(
    const int* __restrict__ mask, float* __restrict__ S)
{
    extern __shared__ __align__(16) unsigned short sm[];
    const uint32_t sb = smem_u32(sm);
    const int t = threadIdx.x, lane = t & 31, w = t >> 5;
    const int wm = w >> 2, wn = w & 3;
    const int z = blockIdx.z, bm = blockIdx.y * 128, bn = blockIdx.x * 128;

    // tile bases (halves): Qh 0, Ql 9216, Kh 18432, Kl 27648
    const uint32_t qh = sb, ql = sb + 9216*2, kh = sb + 18432*2, kl = sb + 27648*2;

    // --- load all 4 tiles via cp.async: 4096 16B-chunks over 512 threads ---
    #pragma unroll
    for (int c = 0; c < 8; c++) {
        const int id   = c * 512 + t;
        const int tile = id >> 10;
        const int row  = (id >> 3) & 127;
        const int seg  = id & 7;
        const __nv_bfloat16* p0 =
            (tile == 0) ? g_Qhi : (tile == 1) ? g_Qlo :
            (tile == 2) ? g_Khi : g_Klo;
        const int rb = (tile < 2) ? bm : bn;
        const __nv_bfloat16* src =
            p0 + ((size_t)z * 2048 + rb + row) * 64 + seg * 8;
        const uint32_t dst = sb + (uint32_t)(tile * 9216 + row * 72 + seg * 8) * 2;
        cpa16(dst, src);
    }
    CP_COMMIT();
    CP_WAIT0();
    __syncthreads();

    // --- MMA mainloop: 4 k16 steps, bf16x3 ---
    float acc[2][4][4];
    #pragma unroll
    for (int i = 0; i < 2; i++)
        #pragma unroll
        for (int j = 0; j < 4; j++)
            #pragma unroll
            for (int q = 0; q < 4; q++) acc[i][j][q] = 0.f;

    #pragma unroll
    for (int k16 = 0; k16 < 4; k16++) {
        const int k0 = k16 * 16;
        uint32_t afh[2][4], afl[2][4], bfh[2][4], bfl[2][4];
        #pragma unroll
        for (int mi = 0; mi < 2; mi++) {
            ldsm4(afh[mi], fa72(qh, wm * 32 + mi * 16, k0, lane));
            ldsm4(afl[mi], fa72(ql, wm * 32 + mi * 16, k0, lane));
        }
        #pragma unroll
        for (int ng = 0; ng < 2; ng++) {
            ldsm4(bfh[ng], fa72(kh, wn * 32 + ng * 16, k0, lane));
            ldsm4(bfl[ng], fa72(kl, wn * 32 + ng * 16, k0, lane));
        }
        #pragma unroll
        for (int mi = 0; mi < 2; mi++)
            #pragma unroll
            for (int nj = 0; nj < 4; nj++) {
                const int ng = nj >> 1, hh = nj & 1;
                mma16816(acc[mi][nj], afh[mi], bfh[ng][hh], bfh[ng][hh + 2]);
                mma16816(acc[mi][nj], afh[mi], bfl[ng][hh], bfl[ng][hh + 2]);
                mma16816(acc[mi][nj], afl[mi], bfh[ng][hh], bfh[ng][hh + 2]);
            }
    }

    // --- epilogue: mask + raw logits + per-(32col) partials ---
    float* Sz = S + (size_t)z * LQ_ * LK_;
    float2* part = g_part + ((size_t)z * 64 + blockIdx.x * 4 + wn) * LQ_;
    #pragma unroll
    for (int mi = 0; mi < 2; mi++)
        #pragma unroll
        for (int half = 0; half < 2; half++) {
            const int r = bm + wm * 32 + mi * 16 + (lane >> 2) + half * 8;
            float v[8];
            #pragma unroll
            for (int nj = 0; nj < 4; nj++) {
                const int c = bn + wn * 32 + nj * 8 + (lane & 3) * 2;
                const int2 mm = *(const int2*)&mask[(size_t)r * LK_ + c];
                v[nj * 2]     = mm.x ? acc[mi][nj][half * 2]     : NEGV;
                v[nj * 2 + 1] = mm.y ? acc[mi][nj][half * 2 + 1] : NEGV;
                *(float2*)&Sz[(size_t)r * LK_ + c] =
                    make_float2(v[nj * 2], v[nj * 2 + 1]);
            }
            float mx = v[0];
            #pragma unroll
            for (int j = 1; j < 8; j++) mx = fmaxf(mx, v[j]);
            mx = fmaxf(mx, __shfl_xor_sync(0xffffffffu, mx, 1));
            mx = fmaxf(mx, __shfl_xor_sync(0xffffffffu, mx, 2));
            float smv = 0.f;
            #pragma unroll
            for (int j = 0; j < 8; j++) smv += __expf(v[j] - mx);
            smv += __shfl_xor_sync(0xffffffffu, smv, 1);
            smv += __shfl_xor_sync(0xffffffffu, smv, 2);
            if ((lane & 3) == 0) part[r] = make_float2(mx, smv);
        }
}

// ---------------------------------------------------------------------------
// Combine 64 partial stats per row -> {rowmax, 1/rowsum}.
// ---------------------------------------------------------------------------
__global__ __launch_bounds__(256) void combine_kernel()
{
    const int idx = blockIdx.x * 256 + threadIdx.x;
    if (idx >= NZ * LQ_) return;
    const int z = idx >> 11, m = idx & 2047;
    const float2* p = g_part + (size_t)z * 64 * LQ_ + m;
    float M = -3.4e38f;
    #pragma unroll 8
    for (int i = 0; i < 64; i++) M = fmaxf(M, p[(size_t)i * LQ_].x);
    float Ssum = 0.f;
    #pragma unroll 8
    for (int i = 0; i < 64; i++) {
        const float2 q = p[(size_t)i * LQ_];
        Ssum += q.y * __expf(q.x - M);
    }
    g_stats[idx] = make_float2(M, 1.0f / Ssum);
}

// ---------------------------------------------------------------------------
// PV fused with normalization (round-7 fp32 f32x2 version).
// ---------------------------------------------------------------------------
__global__ __launch_bounds__(256) void pv_kernel(float* __restrict__ S)
{
    const int z  = blockIdx.y;
    const int bm = blockIdx.x * 128;
    const float* V = g_Vh + (size_t)z * LK_ * HD_;
    float* Sz = S + (size_t)z * LQ_ * LK_;

    __shared__ float Ps[16][132];
    __shared__ float Vs[16][68];
    const int t  = threadIdx.x;
    const int tx = t & 15, ty = t >> 4;
    const int r  = t >> 1, half = t & 1;
    const int vk = t >> 4, vg = t & 15;

    const float2 st = g_stats[(size_t)z * LQ_ + bm + r];

    u64 acc2[8][2];
    #pragma unroll
    for (int i = 0; i < 8; i++) {
        acc2[i][0] = pack2(0.f, 0.f);
        acc2[i][1] = pack2(0.f, 0.f);
    }

    for (int kt = 0; kt < LK_; kt += 16) {
        float* sp = &Sz[(size_t)(bm + r) * LK_ + kt + half * 8];
        float4 s0 = *(const float4*)(sp);
        float4 s1 = *(const float4*)(sp + 4);
        s0.x = __expf(s0.x - st.x) * st.y;
        s0.y = __expf(s0.y - st.x) * st.y;
        s0.z = __expf(s0.z - st.x) * st.y;
        s0.w = __expf(s0.w - st.x) * st.y;
        s1.x = __expf(s1.x - st.x) * st.y;
        s1.y = __expf(s1.y - st.x) * st.y;
        s1.z = __expf(s1.z - st.x) * st.y;
        s1.w = __expf(s1.w - st.x) * st.y;
        *(float4*)(sp)     = s0;             // final normalized scores
        *(float4*)(sp + 4) = s1;
        const int c = half * 8;
        Ps[c+0][r]=s0.x; Ps[c+1][r]=s0.y; Ps[c+2][r]=s0.z; Ps[c+3][r]=s0.w;
        Ps[c+4][r]=s1.x; Ps[c+5][r]=s1.y; Ps[c+6][r]=s1.z; Ps[c+7][r]=s1.w;

        *(float4*)&Vs[vk][vg * 4] = *(const float4*)&V[(size_t)(kt + vk) * HD_ + vg * 4];
        __syncthreads();
        #pragma unroll
        for (int kk = 0; kk < 16; kk++) {
            float4 x0 = *(const float4*)&Ps[kk][ty * 8];
            float4 x1 = *(const float4*)&Ps[kk][ty * 8 + 4];
            float4 b4 = *(const float4*)&Vs[kk][tx * 4];
            const u64 b20 = pack2(b4.x, b4.y);
            const u64 b21 = pack2(b4.z, b4.w);
            float a[8] = {x0.x,x0.y,x0.z,x0.w,x1.x,x1.y,x1.z,x1.w};
            #pragma unroll
            for (int i = 0; i < 8; i++) {
                const u64 a2 = pack2(a[i], a[i]);
                acc2[i][0] = ffma2(a2, b20, acc2[i][0]);
                acc2[i][1] = ffma2(a2, b21, acc2[i][1]);
            }
        }
        __syncthreads();
    }

    const int bb = z >> 4, h = z & 15;
    #pragma unroll
    for (int i = 0; i < 8; i++) {
        const int q = bm + ty * 8 + i;
        float2 p0 = unpack2(acc2[i][0]), p1 = unpack2(acc2[i][1]);
        float4 o = {p0.x, p0.y, p1.x, p1.y};
        *(float4*)&g_Oh[((size_t)bb * LQ_ + q) * HDA + h * HD_ + tx * 4] = o;
    }
}

// ---------------------------------------------------------------------------
// Output GEMM: out = Oh @ wo^T + bo (round-7 version).
// ---------------------------------------------------------------------------
__global__ __launch_bounds__(256) void o_kernel(
    const float* __restrict__ wo, const float* __restrict__ bo,
    float* __restrict__ out)
{
    const int bm = blockIdx.x * 64;
    __shared__ float As[16][68];
    __shared__ float Ws[16][68];
    const int t  = threadIdx.x;
    const int tx = t % 16, ty = t / 16;
    const int lk = t % 16, lr = t / 16;

    u64 acc2[4][2];
    #pragma unroll
    for (int i = 0; i < 4; i++) {
        acc2[i][0] = pack2(0.f, 0.f);
        acc2[i][1] = pack2(0.f, 0.f);
    }

    for (int kt = 0; kt < HDA; kt += 16) {
        #pragma unroll
        for (int i = 0; i < 4; i++) {
            const int m = i * 16 + lr;
            As[lk][m] = g_Oh[(size_t)(bm + m) * HDA + kt + lk];
            Ws[lk][m] = wo  [(size_t)m        * HDA + kt + lk];
        }
        __syncthreads();
        #pragma unroll
        for (int kk = 0; kk < 16; kk++) {
            float a[4], b[4];
            #pragma unroll
            for (int i = 0; i < 4; i++) a[i] = As[kk][ty * 4 + i];
            #pragma unroll
            for (int j = 0; j < 4; j++) b[j] = Ws[kk][tx + 16 * j];
            const u64 b20 = pack2(b[0], b[1]);
            const u64 b21 = pack2(b[2], b[3]);
            #pragma unroll
            for (int i = 0; i < 4; i++) {
                const u64 a2 = pack2(a[i], a[i]);
                acc2[i][0] = ffma2(a2, b20, acc2[i][0]);
                acc2[i][1] = ffma2(a2, b21, acc2[i][1]);
            }
        }
        __syncthreads();
    }

    #pragma unroll
    for (int i = 0; i < 4; i++) {
        const int m = bm + ty * 4 + i;
        float2 p0 = unpack2(acc2[i][0]), p1 = unpack2(acc2[i][1]);
        out[(size_t)m * HD_ + tx]      = p0.x + bo[tx];
        out[(size_t)m * HD_ + tx + 16] = p0.y + bo[tx + 16];
        out[(size_t)m * HD_ + tx + 32] = p1.x + bo[tx + 32];
        out[(size_t)m * HD_ + tx + 48] = p1.y + bo[tx + 48];
    }
}

// ---------------------------------------------------------------------------
extern "C" void kernel_launch(void* const* d_in, const int* in_sizes, int n_in,
                              void* d_out, int out_size)
{
    (void)in_sizes; (void)n_in; (void)out_size;
    const float* q    = (const float*)d_in[0];
    const float* k    = (const float*)d_in[1];
    const float* v    = (const float*)d_in[2];
    const int*   mask = (const int*)  d_in[3];
    const float* wq   = (const float*)d_in[4];
    const float* bq   = (const float*)d_in[5];
    const float* wk   = (const float*)d_in[6];
    const float* bk   = (const float*)d_in[7];
    const float* wv   = (const float*)d_in[8];
    const float* bv   = (const float*)d_in[9];
    const float* wo   = (const float*)d_in[10];
    const float* bo   = (const float*)d_in[11];

    float* out    = (float*)d_out;                       // [B, LQ, 64]
    float* scores = out + (size_t)B_ * LQ_ * HD_;        // [B, H, LQ, LK]

    __nv_bfloat16 *Qhi, *Qlo, *Khi, *Klo;
    float* Vh;
    cudaGetSymbolAddress((void**)&Qhi, g_Qhi);
    cudaGetSymbolAddress((void**)&Qlo, g_Qlo);
    cudaGetSymbolAddress((void**)&Khi, g_Khi);
    cudaGetSymbolAddress((void**)&Klo, g_Klo);
    cudaGetSymbolAddress((void**)&Vh,  g_Vh);

    const int QK_SMEM = 4 * 128 * 72 * 2;                // 73728 B
    cudaFuncSetAttribute(qk_mma, cudaFuncAttributeMaxDynamicSharedMemorySize,
                         QK_SMEM);

    const dim3 blk(256);
    const dim3 gproj(IND / 128, (B_ * LQ_) / 128);       // (8, 64)
    proj_kernel<<<gproj, blk>>>(q, wq, bq, 0.125f, 1, nullptr, Qhi, Qlo);
    proj_kernel<<<gproj, blk>>>(k, wk, bk, 1.0f,   1, nullptr, Khi, Klo);
    proj_kernel<<<gproj, blk>>>(v, wv, bv, 1.0f,   0, Vh, nullptr, nullptr);

    qk_mma<<<dim3(LK_ / 128, LQ_ / 128, NZ), 512, QK_SMEM>>>(mask, scores);

    combine_kernel<<<(NZ * LQ_ + 255) / 256, blk>>>();   // 512 blocks

    const dim3 gpv(LQ_ / 128, NZ);                       // (16, 64)
    pv_kernel<<<gpv, blk>>>(scores);

    o_kernel<<<(B_ * LQ_) / 64, blk>>>(wo, bo, out);     // 128 blocks
}

// round 12
// speedup vs baseline: 1.3797x; 1.0784x over previous
#include <cuda_runtime.h>
#include <cuda_bf16.h>
#include <math.h>
#include <cstdint>

#define B_   4
#define LQ_  2048
#define LK_  2048
#define IND  1024
#define NH_  16
#define HD_  64
#define HDA  1024
#define NZ   (B_*NH_)
#define NEGV (-1e9f)

typedef unsigned long long u64;

// Scratch (device globals)
__device__ __nv_bfloat16 g_Qhi[(size_t)NZ * LQ_ * HD_];  // [z][l][d]
__device__ __nv_bfloat16 g_Qlo[(size_t)NZ * LQ_ * HD_];
__device__ __nv_bfloat16 g_Khi[(size_t)NZ * LK_ * HD_];
__device__ __nv_bfloat16 g_Klo[(size_t)NZ * LK_ * HD_];
__device__ __nv_bfloat16 g_Vthi[(size_t)NZ * HD_ * LK_];  // [z][d][l]
__device__ __nv_bfloat16 g_Vtlo[(size_t)NZ * HD_ * LK_];
__device__ float  g_Vf[(size_t)NZ * LK_ * HD_];          // [z][l][d]
__device__ float  g_Oh[(size_t)B_ * LQ_ * HDA];          // [b][q][h*d]
__device__ float2 g_part[(size_t)NZ * 64 * LQ_];         // per-(z, 32col-tile, row)
__device__ float2 g_stats[(size_t)NZ * LQ_];             // {rowmax, 1/rowsum}

// ---------------- helpers ----------------
__device__ __forceinline__ u64 pack2(float x, float y) {
    u64 r; asm("mov.b64 %0, {%1, %2};" : "=l"(r) : "f"(x), "f"(y)); return r;
}
__device__ __forceinline__ float2 unpack2(u64 v) {
    float x, y; asm("mov.b64 {%0, %1}, %2;" : "=f"(x), "=f"(y) : "l"(v));
    return make_float2(x, y);
}
__device__ __forceinline__ u64 ffma2(u64 a, u64 b, u64 c) {
    u64 d; asm("fma.rn.f32x2 %0, %1, %2, %3;" : "=l"(d) : "l"(a), "l"(b), "l"(c));
    return d;
}
__device__ __forceinline__ uint32_t smem_u32(const void* p) {
    uint32_t a;
    asm("{ .reg .u64 t; cvta.to.shared.u64 t, %1; cvt.u32.u64 %0, t; }" : "=r"(a) : "l"(p));
    return a;
}
__device__ __forceinline__ void cpa16(uint32_t dst, const void* src) {
    asm volatile("cp.async.cg.shared.global [%0], [%1], 16;" :: "r"(dst), "l"(src));
}
#define CP_COMMIT() asm volatile("cp.async.commit_group;" ::: "memory")
#define CP_WAIT0()  asm volatile("cp.async.wait_group 0;" ::: "memory")
#define CP_WAIT1()  asm volatile("cp.async.wait_group 1;" ::: "memory")

__device__ __forceinline__ void ldsm4(uint32_t (&r)[4], uint32_t addr) {
    asm volatile("ldmatrix.sync.aligned.m8n8.x4.shared.b16 {%0,%1,%2,%3}, [%4];"
                 : "=r"(r[0]), "=r"(r[1]), "=r"(r[2]), "=r"(r[3]) : "r"(addr));
}
// fragment addr, [rows][72]-halves tile (144B stride)
__device__ __forceinline__ uint32_t fa72(uint32_t base, int row0, int k0, int lane) {
    const int g = lane >> 3;
    const int row = row0 + (lane & 7) + ((g & 1) << 3);
    const int col = k0 + ((g >> 1) << 3);
    return base + (uint32_t)(row * 72 + col) * 2;
}
// fragment addr, [rows][40]-halves tile (80B stride; conflict-free, 16B aligned)
__device__ __forceinline__ uint32_t fa40(uint32_t base, int row0, int k0, int lane) {
    const int g = lane >> 3;
    const int row = row0 + (lane & 7) + ((g & 1) << 3);
    const int col = k0 + ((g >> 1) << 3);
    return base + (uint32_t)(row * 40 + col) * 2;
}
__device__ __forceinline__ void mma16816(float (&d)[4], const uint32_t (&a)[4],
                                         uint32_t b0, uint32_t b1) {
    asm volatile(
        "mma.sync.aligned.m16n8k16.row.col.f32.bf16.bf16.f32 "
        "{%0,%1,%2,%3},{%4,%5,%6,%7},{%8,%9},{%0,%1,%2,%3};"
        : "+f"(d[0]), "+f"(d[1]), "+f"(d[2]), "+f"(d[3])
        : "r"(a[0]), "r"(a[1]), "r"(a[2]), "r"(a[3]), "r"(b0), "r"(b1));
}
__device__ __forceinline__ void split8(const float* v, uint4& hi, uint4& lo) {
    unsigned short h[8], l[8];
    #pragma unroll
    for (int i = 0; i < 8; i++) {
        __nv_bfloat16 hb = __float2bfloat16_rn(v[i]);
        __nv_bfloat16 lb = __float2bfloat16_rn(v[i] - __bfloat162float(hb));
        h[i] = __bfloat16_as_ushort(hb);
        l[i] = __bfloat16_as_ushort(lb);
    }
    hi.x = h[0] | ((uint32_t)h[1] << 16); hi.y = h[2] | ((uint32_t)h[3] << 16);
    hi.z = h[4] | ((uint32_t)h[5] << 16); hi.w = h[6] | ((uint32_t)h[7] << 16);
    lo.x = l[0] | ((uint32_t)l[1] << 16); lo.y = l[2] | ((uint32_t)l[3] << 16);
    lo.z = l[4] | ((uint32_t)l[5] << 16); lo.w = l[6] | ((uint32_t)l[7] << 16);
}

// ---------------------------------------------------------------------------
// Projection GEMM (fp32 f32x2): Y = alpha*(X@W^T + bias). 128x128x16,
// 8x8 microtile. mode 0: fp32 [z][l][d]. mode 1: bf16 hi/lo [z][l][d].
// ---------------------------------------------------------------------------
__global__ __launch_bounds__(256) void proj_kernel(
    const float* __restrict__ X, const float* __restrict__ W,
    const float* __restrict__ bias, float alpha, int mode,
    float* __restrict__ dstF,
    __nv_bfloat16* __restrict__ dstHi, __nv_bfloat16* __restrict__ dstLo)
{
    const int bm = blockIdx.y * 128;
    const int bn = blockIdx.x * 128;
    __shared__ float As[16][132];
    __shared__ float Bs[16][132];
    const int t  = threadIdx.x;
    const int tx = t & 15, ty = t >> 4;
    const int r  = t >> 1, half = t & 1;

    const float* Ap = X + (size_t)(bm + r) * IND + half * 8;
    const float* Bp = W + (size_t)(bn + r) * IND + half * 8;

    float4 a0 = *(const float4*)(Ap);
    float4 a1 = *(const float4*)(Ap + 4);
    float4 b0 = *(const float4*)(Bp);
    float4 b1 = *(const float4*)(Bp + 4);

    u64 acc2[8][4];
    #pragma unroll
    for (int i = 0; i < 8; i++)
        #pragma unroll
        for (int j = 0; j < 4; j++) acc2[i][j] = pack2(0.f, 0.f);

    for (int kt = 0; kt < IND; kt += 16) {
        const int c = half * 8;
        As[c+0][r]=a0.x; As[c+1][r]=a0.y; As[c+2][r]=a0.z; As[c+3][r]=a0.w;
        As[c+4][r]=a1.x; As[c+5][r]=a1.y; As[c+6][r]=a1.z; As[c+7][r]=a1.w;
        Bs[c+0][r]=b0.x; Bs[c+1][r]=b0.y; Bs[c+2][r]=b0.z; Bs[c+3][r]=b0.w;
        Bs[c+4][r]=b1.x; Bs[c+5][r]=b1.y; Bs[c+6][r]=b1.z; Bs[c+7][r]=b1.w;
        __syncthreads();
        if (kt + 16 < IND) {
            a0 = *(const float4*)(Ap + kt + 16);
            a1 = *(const float4*)(Ap + kt + 20);
            b0 = *(const float4*)(Bp + kt + 16);
            b1 = *(const float4*)(Bp + kt + 20);
        }
        #pragma unroll
        for (int kk = 0; kk < 16; kk++) {
            float4 x0 = *(const float4*)&As[kk][ty * 8];
            float4 x1 = *(const float4*)&As[kk][ty * 8 + 4];
            float4 y0 = *(const float4*)&Bs[kk][tx * 8];
            float4 y1 = *(const float4*)&Bs[kk][tx * 8 + 4];
            u64 b2[4] = {pack2(y0.x, y0.y), pack2(y0.z, y0.w),
                         pack2(y1.x, y1.y), pack2(y1.z, y1.w)};
            float a[8] = {x0.x,x0.y,x0.z,x0.w,x1.x,x1.y,x1.z,x1.w};
            #pragma unroll
            for (int i = 0; i < 8; i++) {
                const u64 a2 = pack2(a[i], a[i]);
                #pragma unroll
                for (int j = 0; j < 4; j++)
                    acc2[i][j] = ffma2(a2, b2[j], acc2[i][j]);
            }
        }
        __syncthreads();
    }

    #pragma unroll
    for (int i = 0; i < 8; i++) {
        const int m  = bm + ty * 8 + i;
        const int bb = m >> 11, l = m & 2047;
        const int n0 = bn + tx * 8;
        const int h  = n0 >> 6, dd = n0 & 63;
        const size_t idx = (((size_t)(bb * NH_ + h) * LK_) + l) * HD_ + dd;
        float2 p0 = unpack2(acc2[i][0]), p1 = unpack2(acc2[i][1]);
        float2 p2 = unpack2(acc2[i][2]), p3 = unpack2(acc2[i][3]);
        float v[8];
        v[0] = alpha * (p0.x + bias[n0+0]);
        v[1] = alpha * (p0.y + bias[n0+1]);
        v[2] = alpha * (p1.x + bias[n0+2]);
        v[3] = alpha * (p1.y + bias[n0+3]);
        v[4] = alpha * (p2.x + bias[n0+4]);
        v[5] = alpha * (p2.y + bias[n0+5]);
        v[6] = alpha * (p3.x + bias[n0+6]);
        v[7] = alpha * (p3.y + bias[n0+7]);
        if (mode == 0) {
            *(float4*)&dstF[idx]     = make_float4(v[0], v[1], v[2], v[3]);
            *(float4*)&dstF[idx + 4] = make_float4(v[4], v[5], v[6], v[7]);
        } else {
            uint4 hi, lo; split8(v, hi, lo);
            *(uint4*)&dstHi[idx] = hi;
            *(uint4*)&dstLo[idx] = lo;
        }
    }
}

// ---------------------------------------------------------------------------
// V transpose: g_Vf [z][l][64] fp32 -> g_Vt{hi,lo} [z][64][l] bf16. (15.6us)
// ---------------------------------------------------------------------------
__global__ __launch_bounds__(256) void vtrans_kernel()
{
    const int z = blockIdx.y, l0 = blockIdx.x * 64;
    __shared__ float tile[64][65];
    const int t = threadIdx.x, row = t >> 2, q = t & 3;
    #pragma unroll
    for (int i = 0; i < 4; i++) {
        float4 v = *(const float4*)&g_Vf[((size_t)z * 2048 + l0 + row) * 64 + q * 16 + i * 4];
        tile[row][q * 16 + i * 4 + 0] = v.x;
        tile[row][q * 16 + i * 4 + 1] = v.y;
        tile[row][q * 16 + i * 4 + 2] = v.z;
        tile[row][q * 16 + i * 4 + 3] = v.w;
    }
    __syncthreads();
    float v[16];
    #pragma unroll
    for (int i = 0; i < 16; i++) v[i] = tile[q * 16 + i][row];
    uint4 h0, l0v, h1, l1;
    split8(v, h0, l0v); split8(v + 8, h1, l1);
    const size_t base = ((size_t)z * 64 + row) * 2048 + l0 + q * 16;
    *(uint4*)&g_Vthi[base]     = h0;  *(uint4*)&g_Vthi[base + 8] = h1;
    *(uint4*)&g_Vtlo[base]     = l0v; *(uint4*)&g_Vtlo[base + 8] = l1;
}

// ---------------------------------------------------------------------------
// QK^T via bf16x3 mma.sync (round-10, unchanged): CTA 128x128, 512 threads.
// ---------------------------------------------------------------------------
__global__ __launch_bounds__(512) void qk_mma(
    const int* __restrict__ mask, float* __restrict__ S)
{
    extern __shared__ __align__(16) unsigned short sm[];
    const uint32_t sb = smem_u32(sm);
    const int t = threadIdx.x, lane = t & 31, w = t >> 5;
    const int wm = w >> 2, wn = w & 3;
    const int z = blockIdx.z, bm = blockIdx.y * 128, bn = blockIdx.x * 128;

    const uint32_t qh = sb, ql = sb + 9216*2, kh = sb + 18432*2, kl = sb + 27648*2;

    #pragma unroll
    for (int c = 0; c < 8; c++) {
        const int id   = c * 512 + t;
        const int tile = id >> 10;
        const int row  = (id >> 3) & 127;
        const int seg  = id & 7;
        const __nv_bfloat16* p0 =
            (tile == 0) ? g_Qhi : (tile == 1) ? g_Qlo :
            (tile == 2) ? g_Khi : g_Klo;
        const int rb = (tile < 2) ? bm : bn;
        const __nv_bfloat16* src =
            p0 + ((size_t)z * 2048 + rb + row) * 64 + seg * 8;
        const uint32_t dst = sb + (uint32_t)(tile * 9216 + row * 72 + seg * 8) * 2;
        cpa16(dst, src);
    }
    CP_COMMIT();
    CP_WAIT0();
    __syncthreads();

    float acc[2][4][4];
    #pragma unroll
    for (int i = 0; i < 2; i++)
        #pragma unroll
        for (int j = 0; j < 4; j++)
            #pragma unroll
            for (int q = 0; q < 4; q++) acc[i][j][q] = 0.f;

    #pragma unroll
    for (int k16 = 0; k16 < 4; k16++) {
        const int k0 = k16 * 16;
        uint32_t afh[2][4], afl[2][4], bfh[2][4], bfl[2][4];
        #pragma unroll
        for (int mi = 0; mi < 2; mi++) {
            ldsm4(afh[mi], fa72(qh, wm * 32 + mi * 16, k0, lane));
            ldsm4(afl[mi], fa72(ql, wm * 32 + mi * 16, k0, lane));
        }
        #pragma unroll
        for (int ng = 0; ng < 2; ng++) {
            ldsm4(bfh[ng], fa72(kh, wn * 32 + ng * 16, k0, lane));
            ldsm4(bfl[ng], fa72(kl, wn * 32 + ng * 16, k0, lane));
        }
        #pragma unroll
        for (int mi = 0; mi < 2; mi++)
            #pragma unroll
            for (int nj = 0; nj < 4; nj++) {
                const int ng = nj >> 1, hh = nj & 1;
                mma16816(acc[mi][nj], afh[mi], bfh[ng][hh], bfh[ng][hh + 2]);
                mma16816(acc[mi][nj], afh[mi], bfl[ng][hh], bfl[ng][hh + 2]);
                mma16816(acc[mi][nj], afl[mi], bfh[ng][hh], bfh[ng][hh + 2]);
            }
    }

    float* Sz = S + (size_t)z * LQ_ * LK_;
    float2* part = g_part + ((size_t)z * 64 + blockIdx.x * 4 + wn) * LQ_;
    #pragma unroll
    for (int mi = 0; mi < 2; mi++)
        #pragma unroll
        for (int half = 0; half < 2; half++) {
            const int r = bm + wm * 32 + mi * 16 + (lane >> 2) + half * 8;
            float v[8];
            #pragma unroll
            for (int nj = 0; nj < 4; nj++) {
                const int c = bn + wn * 32 + nj * 8 + (lane & 3) * 2;
                const int2 mm = *(const int2*)&mask[(size_t)r * LK_ + c];
                v[nj * 2]     = mm.x ? acc[mi][nj][half * 2]     : NEGV;
                v[nj * 2 + 1] = mm.y ? acc[mi][nj][half * 2 + 1] : NEGV;
                *(float2*)&Sz[(size_t)r * LK_ + c] =
                    make_float2(v[nj * 2], v[nj * 2 + 1]);
            }
            float mx = v[0];
            #pragma unroll
            for (int j = 1; j < 8; j++) mx = fmaxf(mx, v[j]);
            mx = fmaxf(mx, __shfl_xor_sync(0xffffffffu, mx, 1));
            mx = fmaxf(mx, __shfl_xor_sync(0xffffffffu, mx, 2));
            float smv = 0.f;
            #pragma unroll
            for (int j = 0; j < 8; j++) smv += __expf(v[j] - mx);
            smv += __shfl_xor_sync(0xffffffffu, smv, 1);
            smv += __shfl_xor_sync(0xffffffffu, smv, 2);
            if ((lane & 3) == 0) part[r] = make_float2(mx, smv);
        }
}

// ---------------------------------------------------------------------------
// Combine 64 partial stats per row -> {rowmax, 1/rowsum}.
// ---------------------------------------------------------------------------
__global__ __launch_bounds__(256) void combine_kernel()
{
    const int idx = blockIdx.x * 256 + threadIdx.x;
    if (idx >= NZ * LQ_) return;
    const int z = idx >> 11, m = idx & 2047;
    const float2* p = g_part + (size_t)z * 64 * LQ_ + m;
    float M = -3.4e38f;
    #pragma unroll 8
    for (int i = 0; i < 64; i++) M = fmaxf(M, p[(size_t)i * LQ_].x);
    float Ssum = 0.f;
    #pragma unroll 8
    for (int i = 0; i < 64; i++) {
        const float2 q = p[(size_t)i * LQ_];
        Ssum += q.y * __expf(q.x - M);
    }
    g_stats[idx] = make_float2(M, 1.0f / Ssum);
}

// ---------------------------------------------------------------------------
// PV via bf16x3 mma.sync: CTA 128(q) x 64(d), K-loop 2048 tokens in 32-chunks.
// 256 threads = 8 warps (4m x 2n), warp tile 32x32.
// P (from normalized S) and V (cp.async) double-buffered; 1 sync/iter.
// smem halves layout: P[2]{hi,lo}[128][40], V[2]{hi,lo}[64][40].
// ---------------------------------------------------------------------------
#define PV_P(b, h)  ((uint32_t)(((b) * 2 + (h)) * 5120))        // 128*40
#define PV_V(b, h)  ((uint32_t)(20480 + ((b) * 2 + (h)) * 2560)) // 64*40
#define PV_SMEM     ((20480 + 4 * 2560) * 2)                     // 61440 B

__global__ __launch_bounds__(256) void pv_mma(float* __restrict__ S)
{
    extern __shared__ __align__(16) unsigned short sm[];
    const uint32_t sb = smem_u32(sm);
    const int t = threadIdx.x, lane = t & 31, w = t >> 5;
    const int wm = w >> 1, wn = w & 1;
    const int z = blockIdx.y, bm = blockIdx.x * 128;

    const int r = t >> 1, half = t & 1;
    const float2 st = g_stats[(size_t)z * LQ_ + bm + r];
    float* Sr = S + (size_t)z * LQ_ * LK_ + (size_t)(bm + r) * LK_;

    // V loader: 2 chunks per thread per buffer fill
    const __nv_bfloat16* Vh0 = g_Vthi + (size_t)z * 64 * 2048;
    const __nv_bfloat16* Vl0 = g_Vtlo + (size_t)z * 64 * 2048;

    float acc[2][4][4];
    #pragma unroll
    for (int i = 0; i < 2; i++)
        #pragma unroll
        for (int j = 0; j < 4; j++)
            #pragma unroll
            for (int q = 0; q < 4; q++) acc[i][j][q] = 0.f;

    // prefetch V chunk 0 into buffer 0
    {
        #pragma unroll
        for (int c = 0; c < 2; c++) {
            const int id = c * 256 + t;          // 0..511
            const int hl = id >> 8;              // 0=hi, 1=lo
            const int row = (id >> 2) & 63;
            const int seg = id & 3;
            const __nv_bfloat16* src =
                (hl ? Vl0 : Vh0) + (size_t)row * 2048 + 0 + seg * 8;
            cpa16(sb + (PV_V(0, hl) + (uint32_t)(row * 40 + seg * 8)) * 2, src);
        }
        CP_COMMIT();
    }

    for (int it = 0; it < 64; it++) {
        const int kt = it * 32;
        const int pb = it & 1;
        // stage P: read S 16 floats, exp-normalize, write back, split, STS
        {
            float v[8]; uint4 hi, lo;
            #pragma unroll
            for (int s = 0; s < 2; s++) {
                float* sp = Sr + kt + half * 16 + s * 8;
                *(float4*)v       = *(const float4*)(sp);
                *(float4*)(v + 4) = *(const float4*)(sp + 4);
                #pragma unroll
                for (int j = 0; j < 8; j++) v[j] = __expf(v[j] - st.x) * st.y;
                *(float4*)(sp)     = make_float4(v[0], v[1], v[2], v[3]);
                *(float4*)(sp + 4) = make_float4(v[4], v[5], v[6], v[7]);
                split8(v, hi, lo);
                const uint32_t off = (uint32_t)(r * 40 + half * 16 + s * 8) * 2;
                *(uint4*)((char*)sm + (PV_P(pb, 0)) * 2 + off) = hi;
                *(uint4*)((char*)sm + (PV_P(pb, 1)) * 2 + off) = lo;
            }
        }
        // prefetch V chunk it+1
        if (it + 1 < 64) {
            const int vb = (it + 1) & 1;
            const int kn = (it + 1) * 32;
            #pragma unroll
            for (int c = 0; c < 2; c++) {
                const int id = c * 256 + t;
                const int hl = id >> 8;
                const int row = (id >> 2) & 63;
                const int seg = id & 3;
                const __nv_bfloat16* src =
                    (hl ? Vl0 : Vh0) + (size_t)row * 2048 + kn + seg * 8;
                cpa16(sb + (PV_V(vb, hl) + (uint32_t)(row * 40 + seg * 8)) * 2, src);
            }
            CP_COMMIT();
            CP_WAIT1();   // V chunk `it` complete
        } else {
            CP_WAIT0();
        }
        __syncthreads();

        // MMA on P[pb], V[pb]
        const uint32_t ph = sb + PV_P(pb, 0) * 2, pl = sb + PV_P(pb, 1) * 2;
        const uint32_t vh = sb + PV_V(pb, 0) * 2, vl = sb + PV_V(pb, 1) * 2;
        #pragma unroll
        for (int k16 = 0; k16 < 2; k16++) {
            const int k0 = k16 * 16;
            uint32_t afh[2][4], afl[2][4], bfh[2][4], bfl[2][4];
            #pragma unroll
            for (int mi = 0; mi < 2; mi++) {
                ldsm4(afh[mi], fa40(ph, wm * 32 + mi * 16, k0, lane));
                ldsm4(afl[mi], fa40(pl, wm * 32 + mi * 16, k0, lane));
            }
            #pragma unroll
            for (int ng = 0; ng < 2; ng++) {
                ldsm4(bfh[ng], fa40(vh, wn * 32 + ng * 16, k0, lane));
                ldsm4(bfl[ng], fa40(vl, wn * 32 + ng * 16, k0, lane));
            }
            #pragma unroll
            for (int mi = 0; mi < 2; mi++)
                #pragma unroll
                for (int nj = 0; nj < 4; nj++) {
                    const int ng = nj >> 1, hh = nj & 1;
                    mma16816(acc[mi][nj], afh[mi], bfh[ng][hh], bfh[ng][hh + 2]);
                    mma16816(acc[mi][nj], afh[mi], bfl[ng][hh], bfl[ng][hh + 2]);
                    mma16816(acc[mi][nj], afl[mi], bfh[ng][hh], bfh[ng][hh + 2]);
                }
        }
        __syncthreads();
    }

    const int bb = z >> 4, h = z & 15;
    #pragma unroll
    for (int mi = 0; mi < 2; mi++)
        #pragma unroll
        for (int nj = 0; nj < 4; nj++) {
            const int r0 = bm + wm * 32 + mi * 16 + (lane >> 2);
            const int c  = wn * 32 + nj * 8 + (lane & 3) * 2;
            #pragma unroll
            for (int hf = 0; hf < 2; hf++) {
                const int rr = r0 + hf * 8;
                *(float2*)&g_Oh[((size_t)bb * LQ_ + rr) * HDA + h * 64 + c] =
                    make_float2(acc[mi][nj][hf * 2], acc[mi][nj][hf * 2 + 1]);
            }
        }
}

// ---------------------------------------------------------------------------
// Output GEMM: out = Oh @ wo^T + bo. (unchanged)
// ---------------------------------------------------------------------------
__global__ __launch_bounds__(256) void o_kernel(
    const float* __restrict__ wo, const float* __restrict__ bo,
    float* __restrict__ out)
{
    const int bm = blockIdx.x * 64;
    __shared__ float As[16][68];
    __shared__ float Ws[16][68];
    const int t  = threadIdx.x;
    const int tx = t % 16, ty = t / 16;
    const int lk = t % 16, lr = t / 16;

    u64 acc2[4][2];
    #pragma unroll
    for (int i = 0; i < 4; i++) {
        acc2[i][0] = pack2(0.f, 0.f);
        acc2[i][1] = pack2(0.f, 0.f);
    }

    for (int kt = 0; kt < HDA; kt += 16) {
        #pragma unroll
        for (int i = 0; i < 4; i++) {
            const int m = i * 16 + lr;
            As[lk][m] = g_Oh[(size_t)(bm + m) * HDA + kt + lk];
            Ws[lk][m] = wo  [(size_t)m        * HDA + kt + lk];
        }
        __syncthreads();
        #pragma unroll
        for (int kk = 0; kk < 16; kk++) {
            float a[4], b[4];
            #pragma unroll
            for (int i = 0; i < 4; i++) a[i] = As[kk][ty * 4 + i];
            #pragma unroll
            for (int j = 0; j < 4; j++) b[j] = Ws[kk][tx + 16 * j];
            const u64 b20 = pack2(b[0], b[1]);
            const u64 b21 = pack2(b[2], b[3]);
            #pragma unroll
            for (int i = 0; i < 4; i++) {
                const u64 a2 = pack2(a[i], a[i]);
                acc2[i][0] = ffma2(a2, b20, acc2[i][0]);
                acc2[i][1] = ffma2(a2, b21, acc2[i][1]);
            }
        }
        __syncthreads();
    }

    #pragma unroll
    for (int i = 0; i < 4; i++) {
        const int m = bm + ty * 4 + i;
        float2 p0 = unpack2(acc2[i][0]), p1 = unpack2(acc2[i][1]);
        out[(size_t)m * HD_ + tx]      = p0.x + bo[tx];
        out[(size_t)m * HD_ + tx + 16] = p0.y + bo[tx + 16];
        out[(size_t)m * HD_ + tx + 32] = p1.x + bo[tx + 32];
        out[(size_t)m * HD_ + tx + 48] = p1.y + bo[tx + 48];
    }
}

// ---------------------------------------------------------------------------
extern "C" void kernel_launch(void* const* d_in, const int* in_sizes, int n_in,
                              void* d_out, int out_size)
{
    (void)in_sizes; (void)n_in; (void)out_size;
    const float* q    = (const float*)d_in[0];
    const float* k    = (const float*)d_in[1];
    const float* v    = (const float*)d_in[2];
    const int*   mask = (const int*)  d_in[3];
    const float* wq   = (const float*)d_in[4];
    const float* bq   = (const float*)d_in[5];
    const float* wk   = (const float*)d_in[6];
    const float* bk   = (const float*)d_in[7];
    const float* wv   = (const float*)d_in[8];
    const float* bv   = (const float*)d_in[9];
    const float* wo   = (const float*)d_in[10];
    const float* bo   = (const float*)d_in[11];

    float* out    = (float*)d_out;                       // [B, LQ, 64]
    float* scores = out + (size_t)B_ * LQ_ * HD_;        // [B, H, LQ, LK]

    __nv_bfloat16 *Qhi, *Qlo, *Khi, *Klo;
    float* Vf;
    cudaGetSymbolAddress((void**)&Qhi, g_Qhi);
    cudaGetSymbolAddress((void**)&Qlo, g_Qlo);
    cudaGetSymbolAddress((void**)&Khi, g_Khi);
    cudaGetSymbolAddress((void**)&Klo, g_Klo);
    cudaGetSymbolAddress((void**)&Vf,  g_Vf);

    const int QK_SMEM = 4 * 128 * 72 * 2;                // 73728 B
    cudaFuncSetAttribute(qk_mma, cudaFuncAttributeMaxDynamicSharedMemorySize,
                         QK_SMEM);
    cudaFuncSetAttribute(pv_mma, cudaFuncAttributeMaxDynamicSharedMemorySize,
                         PV_SMEM);

    const dim3 blk(256);
    const dim3 gproj(IND / 128, (B_ * LQ_) / 128);       // (8, 64)
    proj_kernel<<<gproj, blk>>>(q, wq, bq, 0.125f, 1, nullptr, Qhi, Qlo);
    proj_kernel<<<gproj, blk>>>(k, wk, bk, 1.0f,   1, nullptr, Khi, Klo);
    proj_kernel<<<gproj, blk>>>(v, wv, bv, 1.0f,   0, Vf, nullptr, nullptr);

    vtrans_kernel<<<dim3(LK_ / 64, NZ), blk>>>();        // (32, 64)

    qk_mma<<<dim3(LK_ / 128, LQ_ / 128, NZ), 512, QK_SMEM>>>(mask, scores);

    combine_kernel<<<(NZ * LQ_ + 255) / 256, blk>>>();   // 512 blocks

    pv_mma<<<dim3(LQ_ / 128, NZ), blk, PV_SMEM>>>(scores);

    o_kernel<<<(B_ * LQ_) / 64, blk>>>(wo, bo, out);     // 128 blocks
}

// round 13
// speedup vs baseline: 1.8780x; 1.3612x over previous
#include <cuda_runtime.h>
#include <cuda_bf16.h>
#include <math.h>
#include <cstdint>

#define B_   4
#define LQ_  2048
#define LK_  2048
#define IND  1024
#define NH_  16
#define HD_  64
#define HDA  1024
#define NZ   (B_*NH_)
#define NEGV (-1e9f)

typedef unsigned long long u64;

// Scratch (device globals)
__device__ __nv_bfloat16 g_Xhi[(size_t)B_ * LQ_ * IND];  // split input [m][k]
__device__ __nv_bfloat16 g_Xlo[(size_t)B_ * LQ_ * IND];
__device__ __nv_bfloat16 g_Whi[(size_t)IND * IND];       // split weight [n][k]
__device__ __nv_bfloat16 g_Wlo[(size_t)IND * IND];
__device__ __nv_bfloat16 g_Qhi[(size_t)NZ * LQ_ * HD_];  // [z][l][d]
__device__ __nv_bfloat16 g_Qlo[(size_t)NZ * LQ_ * HD_];
__device__ __nv_bfloat16 g_Khi[(size_t)NZ * LK_ * HD_];
__device__ __nv_bfloat16 g_Klo[(size_t)NZ * LK_ * HD_];
__device__ __nv_bfloat16 g_Vthi[(size_t)NZ * HD_ * LK_]; // [z][d][l]
__device__ __nv_bfloat16 g_Vtlo[(size_t)NZ * HD_ * LK_];
__device__ float  g_Vf[(size_t)NZ * LK_ * HD_];          // [z][l][d]
__device__ float  g_Oh[(size_t)B_ * LQ_ * HDA];          // [b][q][h*d]
__device__ float2 g_part[(size_t)NZ * 64 * LQ_];
__device__ float2 g_stats[(size_t)NZ * LQ_];

// ---------------- helpers ----------------
__device__ __forceinline__ u64 pack2(float x, float y) {
    u64 r; asm("mov.b64 %0, {%1, %2};" : "=l"(r) : "f"(x), "f"(y)); return r;
}
__device__ __forceinline__ float2 unpack2(u64 v) {
    float x, y; asm("mov.b64 {%0, %1}, %2;" : "=f"(x), "=f"(y) : "l"(v));
    return make_float2(x, y);
}
__device__ __forceinline__ u64 ffma2(u64 a, u64 b, u64 c) {
    u64 d; asm("fma.rn.f32x2 %0, %1, %2, %3;" : "=l"(d) : "l"(a), "l"(b), "l"(c));
    return d;
}
__device__ __forceinline__ uint32_t smem_u32(const void* p) {
    uint32_t a;
    asm("{ .reg .u64 t; cvta.to.shared.u64 t, %1; cvt.u32.u64 %0, t; }" : "=r"(a) : "l"(p));
    return a;
}
__device__ __forceinline__ void cpa16(uint32_t dst, const void* src) {
    asm volatile("cp.async.cg.shared.global [%0], [%1], 16;" :: "r"(dst), "l"(src));
}
#define CP_COMMIT() asm volatile("cp.async.commit_group;" ::: "memory")
#define CP_WAIT0()  asm volatile("cp.async.wait_group 0;" ::: "memory")
#define CP_WAIT1()  asm volatile("cp.async.wait_group 1;" ::: "memory")

__device__ __forceinline__ void ldsm4(uint32_t (&r)[4], uint32_t addr) {
    asm volatile("ldmatrix.sync.aligned.m8n8.x4.shared.b16 {%0,%1,%2,%3}, [%4];"
                 : "=r"(r[0]), "=r"(r[1]), "=r"(r[2]), "=r"(r[3]) : "r"(addr));
}
__device__ __forceinline__ uint32_t fa72(uint32_t base, int row0, int k0, int lane) {
    const int g = lane >> 3;
    const int row = row0 + (lane & 7) + ((g & 1) << 3);
    const int col = k0 + ((g >> 1) << 3);
    return base + (uint32_t)(row * 72 + col) * 2;
}
__device__ __forceinline__ uint32_t fa40(uint32_t base, int row0, int k0, int lane) {
    const int g = lane >> 3;
    const int row = row0 + (lane & 7) + ((g & 1) << 3);
    const int col = k0 + ((g >> 1) << 3);
    return base + (uint32_t)(row * 40 + col) * 2;
}
__device__ __forceinline__ void mma16816(float (&d)[4], const uint32_t (&a)[4],
                                         uint32_t b0, uint32_t b1) {
    asm volatile(
        "mma.sync.aligned.m16n8k16.row.col.f32.bf16.bf16.f32 "
        "{%0,%1,%2,%3},{%4,%5,%6,%7},{%8,%9},{%0,%1,%2,%3};"
        : "+f"(d[0]), "+f"(d[1]), "+f"(d[2]), "+f"(d[3])
        : "r"(a[0]), "r"(a[1]), "r"(a[2]), "r"(a[3]), "r"(b0), "r"(b1));
}
__device__ __forceinline__ void split8(const float* v, uint4& hi, uint4& lo) {
    unsigned short h[8], l[8];
    #pragma unroll
    for (int i = 0; i < 8; i++) {
        __nv_bfloat16 hb = __float2bfloat16_rn(v[i]);
        __nv_bfloat16 lb = __float2bfloat16_rn(v[i] - __bfloat162float(hb));
        h[i] = __bfloat16_as_ushort(hb);
        l[i] = __bfloat16_as_ushort(lb);
    }
    hi.x = h[0] | ((uint32_t)h[1] << 16); hi.y = h[2] | ((uint32_t)h[3] << 16);
    hi.z = h[4] | ((uint32_t)h[5] << 16); hi.w = h[6] | ((uint32_t)h[7] << 16);
    lo.x = l[0] | ((uint32_t)l[1] << 16); lo.y = l[2] | ((uint32_t)l[3] << 16);
    lo.z = l[4] | ((uint32_t)l[5] << 16); lo.w = l[6] | ((uint32_t)l[7] << 16);
}

// ---------------------------------------------------------------------------
// Split fp32 -> bf16 hi/lo (streaming).
// ---------------------------------------------------------------------------
__global__ __launch_bounds__(256) void split_kernel(
    const float* __restrict__ x, __nv_bfloat16* __restrict__ hi,
    __nv_bfloat16* __restrict__ lo, int n8)
{
    const int i = blockIdx.x * 256 + threadIdx.x;
    if (i >= n8) return;
    float v[8];
    *(float4*)v       = *(const float4*)(x + (size_t)i * 8);
    *(float4*)(v + 4) = *(const float4*)(x + (size_t)i * 8 + 4);
    uint4 h, l; split8(v, h, l);
    *(uint4*)(hi + (size_t)i * 8) = h;
    *(uint4*)(lo + (size_t)i * 8) = l;
}

// ---------------------------------------------------------------------------
// Projection via bf16x3 mma.sync: CTA 128x128, 512 threads (16 warps, 4x4),
// K=1024 in 32-chunks, double-buffered cp.async.
// smem: [buf][Ah,Al,Bh,Bl] tiles of [128][40] halves = 81920 B.
// mode 0: fp32 [z][l][d] (V). mode 1: bf16 hi/lo [z][l][d] (Q/K).
// ---------------------------------------------------------------------------
#define PJ_TILE(b, tI) ((uint32_t)(((b) * 4 + (tI)) * 5120))
#define PJ_SMEM (8 * 5120 * 2)

__device__ __forceinline__ void proj_load_chunk(
    uint32_t sb, int b, int kt, int t, int bm, int bn)
{
    #pragma unroll
    for (int c = 0; c < 4; c++) {
        const int id = c * 512 + t;
        const int tile = id >> 9;
        const int row = (id >> 2) & 127;
        const int seg = id & 3;
        const __nv_bfloat16* p =
            (tile == 0) ? g_Xhi : (tile == 1) ? g_Xlo :
            (tile == 2) ? g_Whi : g_Wlo;
        const int rb = (tile < 2) ? bm : bn;
        const __nv_bfloat16* src = p + (size_t)(rb + row) * IND + kt + seg * 8;
        cpa16(sb + (PJ_TILE(b, tile) + (uint32_t)(row * 40 + seg * 8)) * 2, src);
    }
}

__global__ __launch_bounds__(512) void proj_mma(
    const float* __restrict__ bias, float alpha, int mode,
    float* __restrict__ dstF,
    __nv_bfloat16* __restrict__ dstHi, __nv_bfloat16* __restrict__ dstLo)
{
    extern __shared__ __align__(16) unsigned short sm[];
    const uint32_t sb = smem_u32(sm);
    const int t = threadIdx.x, lane = t & 31, w = t >> 5;
    const int wm = w >> 2, wn = w & 3;
    const int bm = blockIdx.y * 128, bn = blockIdx.x * 128;

    float acc[2][4][4];
    #pragma unroll
    for (int i = 0; i < 2; i++)
        #pragma unroll
        for (int j = 0; j < 4; j++)
            #pragma unroll
            for (int q = 0; q < 4; q++) acc[i][j][q] = 0.f;

    proj_load_chunk(sb, 0, 0, t, bm, bn);
    CP_COMMIT();

    for (int it = 0; it < 32; it++) {
        if (it + 1 < 32) {
            proj_load_chunk(sb, (it + 1) & 1, (it + 1) * 32, t, bm, bn);
            CP_COMMIT();
            CP_WAIT1();
        } else {
            CP_WAIT0();
        }
        __syncthreads();
        const int b = it & 1;
        const uint32_t ah = sb + PJ_TILE(b, 0) * 2, al = sb + PJ_TILE(b, 1) * 2;
        const uint32_t bh = sb + PJ_TILE(b, 2) * 2, bl = sb + PJ_TILE(b, 3) * 2;
        #pragma unroll
        for (int k16 = 0; k16 < 2; k16++) {
            const int k0 = k16 * 16;
            uint32_t afh[2][4], afl[2][4], bfh[2][4], bfl[2][4];
            #pragma unroll
            for (int mi = 0; mi < 2; mi++) {
                ldsm4(afh[mi], fa40(ah, wm * 32 + mi * 16, k0, lane));
                ldsm4(afl[mi], fa40(al, wm * 32 + mi * 16, k0, lane));
            }
            #pragma unroll
            for (int ng = 0; ng < 2; ng++) {
                ldsm4(bfh[ng], fa40(bh, wn * 32 + ng * 16, k0, lane));
                ldsm4(bfl[ng], fa40(bl, wn * 32 + ng * 16, k0, lane));
            }
            #pragma unroll
            for (int mi = 0; mi < 2; mi++)
                #pragma unroll
                for (int nj = 0; nj < 4; nj++) {
                    const int ng = nj >> 1, hh = nj & 1;
                    mma16816(acc[mi][nj], afh[mi], bfh[ng][hh], bfh[ng][hh + 2]);
                    mma16816(acc[mi][nj], afh[mi], bfl[ng][hh], bfl[ng][hh + 2]);
                    mma16816(acc[mi][nj], afl[mi], bfh[ng][hh], bfh[ng][hh + 2]);
                }
        }
        __syncthreads();
    }

    // epilogue: alpha*(acc + bias) scattered to [z][l][d]
    #pragma unroll
    for (int mi = 0; mi < 2; mi++)
        #pragma unroll
        for (int half = 0; half < 2; half++) {
            const int m = bm + wm * 32 + mi * 16 + (lane >> 2) + half * 8;
            const int bb = m >> 11, l = m & 2047;
            #pragma unroll
            for (int nj = 0; nj < 4; nj++) {
                const int c = bn + wn * 32 + nj * 8 + (lane & 3) * 2;
                const int h = c >> 6, dd = c & 63;
                const size_t idx =
                    (((size_t)(bb * NH_ + h)) * 2048 + l) * 64 + dd;
                const float v0 = alpha * (acc[mi][nj][half * 2]     + bias[c]);
                const float v1 = alpha * (acc[mi][nj][half * 2 + 1] + bias[c + 1]);
                if (mode == 0) {
                    *(float2*)&dstF[idx] = make_float2(v0, v1);
                } else {
                    __nv_bfloat16 h0 = __float2bfloat16_rn(v0);
                    __nv_bfloat16 h1 = __float2bfloat16_rn(v1);
                    __nv_bfloat16 l0 = __float2bfloat16_rn(v0 - __bfloat162float(h0));
                    __nv_bfloat16 l1 = __float2bfloat16_rn(v1 - __bfloat162float(h1));
                    *(uint32_t*)&dstHi[idx] =
                        (uint32_t)__bfloat16_as_ushort(h0) |
                        ((uint32_t)__bfloat16_as_ushort(h1) << 16);
                    *(uint32_t*)&dstLo[idx] =
                        (uint32_t)__bfloat16_as_ushort(l0) |
                        ((uint32_t)__bfloat16_as_ushort(l1) << 16);
                }
            }
        }
}

// ---------------------------------------------------------------------------
// V transpose: g_Vf [z][l][64] fp32 -> g_Vt{hi,lo} [z][64][l] bf16.
// ---------------------------------------------------------------------------
__global__ __launch_bounds__(256) void vtrans_kernel()
{
    const int z = blockIdx.y, l0 = blockIdx.x * 64;
    __shared__ float tile[64][65];
    const int t = threadIdx.x, row = t >> 2, q = t & 3;
    #pragma unroll
    for (int i = 0; i < 4; i++) {
        float4 v = *(const float4*)&g_Vf[((size_t)z * 2048 + l0 + row) * 64 + q * 16 + i * 4];
        tile[row][q * 16 + i * 4 + 0] = v.x;
        tile[row][q * 16 + i * 4 + 1] = v.y;
        tile[row][q * 16 + i * 4 + 2] = v.z;
        tile[row][q * 16 + i * 4 + 3] = v.w;
    }
    __syncthreads();
    float v[16];
    #pragma unroll
    for (int i = 0; i < 16; i++) v[i] = tile[q * 16 + i][row];
    uint4 h0, l0v, h1, l1;
    split8(v, h0, l0v); split8(v + 8, h1, l1);
    const size_t base = ((size_t)z * 64 + row) * 2048 + l0 + q * 16;
    *(uint4*)&g_Vthi[base]     = h0;  *(uint4*)&g_Vthi[base + 8] = h1;
    *(uint4*)&g_Vtlo[base]     = l0v; *(uint4*)&g_Vtlo[base + 8] = l1;
}

// ---------------------------------------------------------------------------
// QK^T via bf16x3 mma.sync (unchanged from round 10).
// ---------------------------------------------------------------------------
__global__ __launch_bounds__(512) void qk_mma(
    const int* __restrict__ mask, float* __restrict__ S)
{
    extern __shared__ __align__(16) unsigned short sm[];
    const uint32_t sb = smem_u32(sm);
    const int t = threadIdx.x, lane = t & 31, w = t >> 5;
    const int wm = w >> 2, wn = w & 3;
    const int z = blockIdx.z, bm = blockIdx.y * 128, bn = blockIdx.x * 128;

    const uint32_t qh = sb, ql = sb + 9216*2, kh = sb + 18432*2, kl = sb + 27648*2;

    #pragma unroll
    for (int c = 0; c < 8; c++) {
        const int id   = c * 512 + t;
        const int tile = id >> 10;
        const int row  = (id >> 3) & 127;
        const int seg  = id & 7;
        const __nv_bfloat16* p0 =
            (tile == 0) ? g_Qhi : (tile == 1) ? g_Qlo :
            (tile == 2) ? g_Khi : g_Klo;
        const int rb = (tile < 2) ? bm : bn;
        const __nv_bfloat16* src =
            p0 + ((size_t)z * 2048 + rb + row) * 64 + seg * 8;
        const uint32_t dst = sb + (uint32_t)(tile * 9216 + row * 72 + seg * 8) * 2;
        cpa16(dst, src);
    }
    CP_COMMIT();
    CP_WAIT0();
    __syncthreads();

    float acc[2][4][4];
    #pragma unroll
    for (int i = 0; i < 2; i++)
        #pragma unroll
        for (int j = 0; j < 4; j++)
            #pragma unroll
            for (int q = 0; q < 4; q++) acc[i][j][q] = 0.f;

    #pragma unroll
    for (int k16 = 0; k16 < 4; k16++) {
        const int k0 = k16 * 16;
        uint32_t afh[2][4], afl[2][4], bfh[2][4], bfl[2][4];
        #pragma unroll
        for (int mi = 0; mi < 2; mi++) {
            ldsm4(afh[mi], fa72(qh, wm * 32 + mi * 16, k0, lane));
            ldsm4(afl[mi], fa72(ql, wm * 32 + mi * 16, k0, lane));
        }
        #pragma unroll
        for (int ng = 0; ng < 2; ng++) {
            ldsm4(bfh[ng], fa72(kh, wn * 32 + ng * 16, k0, lane));
            ldsm4(bfl[ng], fa72(kl, wn * 32 + ng * 16, k0, lane));
        }
        #pragma unroll
        for (int mi = 0; mi < 2; mi++)
            #pragma unroll
            for (int nj = 0; nj < 4; nj++) {
                const int ng = nj >> 1, hh = nj & 1;
                mma16816(acc[mi][nj], afh[mi], bfh[ng][hh], bfh[ng][hh + 2]);
                mma16816(acc[mi][nj], afh[mi], bfl[ng][hh], bfl[ng][hh + 2]);
                mma16816(acc[mi][nj], afl[mi], bfh[ng][hh], bfh[ng][hh + 2]);
            }
    }

    float* Sz = S + (size_t)z * LQ_ * LK_;
    float2* part = g_part + ((size_t)z * 64 + blockIdx.x * 4 + wn) * LQ_;
    #pragma unroll
    for (int mi = 0; mi < 2; mi++)
        #pragma unroll
        for (int half = 0; half < 2; half++) {
            const int r = bm + wm * 32 + mi * 16 + (lane >> 2) + half * 8;
            float v[8];
            #pragma unroll
            for (int nj = 0; nj < 4; nj++) {
                const int c = bn + wn * 32 + nj * 8 + (lane & 3) * 2;
                const int2 mm = *(const int2*)&mask[(size_t)r * LK_ + c];
                v[nj * 2]     = mm.x ? acc[mi][nj][half * 2]     : NEGV;
                v[nj * 2 + 1] = mm.y ? acc[mi][nj][half * 2 + 1] : NEGV;
                *(float2*)&Sz[(size_t)r * LK_ + c] =
                    make_float2(v[nj * 2], v[nj * 2 + 1]);
            }
            float mx = v[0];
            #pragma unroll
            for (int j = 1; j < 8; j++) mx = fmaxf(mx, v[j]);
            mx = fmaxf(mx, __shfl_xor_sync(0xffffffffu, mx, 1));
            mx = fmaxf(mx, __shfl_xor_sync(0xffffffffu, mx, 2));
            float smv = 0.f;
            #pragma unroll
            for (int j = 0; j < 8; j++) smv += __expf(v[j] - mx);
            smv += __shfl_xor_sync(0xffffffffu, smv, 1);
            smv += __shfl_xor_sync(0xffffffffu, smv, 2);
            if ((lane & 3) == 0) part[r] = make_float2(mx, smv);
        }
}

// ---------------------------------------------------------------------------
// Combine 64 partial stats per row -> {rowmax, 1/rowsum}.
// ---------------------------------------------------------------------------
__global__ __launch_bounds__(256) void combine_kernel()
{
    const int idx = blockIdx.x * 256 + threadIdx.x;
    if (idx >= NZ * LQ_) return;
    const int z = idx >> 11, m = idx & 2047;
    const float2* p = g_part + (size_t)z * 64 * LQ_ + m;
    float M = -3.4e38f;
    #pragma unroll 8
    for (int i = 0; i < 64; i++) M = fmaxf(M, p[(size_t)i * LQ_].x);
    float Ssum = 0.f;
    #pragma unroll 8
    for (int i = 0; i < 64; i++) {
        const float2 q = p[(size_t)i * LQ_];
        Ssum += q.y * __expf(q.x - M);
    }
    g_stats[idx] = make_float2(M, 1.0f / Ssum);
}

// ---------------------------------------------------------------------------
// PV via bf16x3 mma.sync with register S-prefetch.
// CTA 128(q) x 64(d), 256 threads (8 warps, 4m x 2n), 64 chunks of 32 tokens.
// ---------------------------------------------------------------------------
#define PV_P(b, h)  ((uint32_t)(((b) * 2 + (h)) * 5120))
#define PV_V(b, h)  ((uint32_t)(20480 + ((b) * 2 + (h)) * 2560))
#define PV_SMEM     ((20480 + 4 * 2560) * 2)

__global__ __launch_bounds__(256) void pv_mma(float* __restrict__ S)
{
    extern __shared__ __align__(16) unsigned short sm[];
    const uint32_t sb = smem_u32(sm);
    const int t = threadIdx.x, lane = t & 31, w = t >> 5;
    const int wm = w >> 1, wn = w & 1;
    const int z = blockIdx.y, bm = blockIdx.x * 128;

    const int r = t >> 1, half = t & 1;
    const float2 st = g_stats[(size_t)z * LQ_ + bm + r];
    float* Sr = S + (size_t)z * LQ_ * LK_ + (size_t)(bm + r) * LK_;

    const __nv_bfloat16* Vh0 = g_Vthi + (size_t)z * 64 * 2048;
    const __nv_bfloat16* Vl0 = g_Vtlo + (size_t)z * 64 * 2048;

    float acc[2][4][4];
    #pragma unroll
    for (int i = 0; i < 2; i++)
        #pragma unroll
        for (int j = 0; j < 4; j++)
            #pragma unroll
            for (int q = 0; q < 4; q++) acc[i][j][q] = 0.f;

    // prefetch V chunk 0
    {
        #pragma unroll
        for (int c = 0; c < 2; c++) {
            const int id = c * 256 + t;
            const int hl = id >> 8;
            const int row = (id >> 2) & 63;
            const int seg = id & 3;
            const __nv_bfloat16* src =
                (hl ? Vl0 : Vh0) + (size_t)row * 2048 + 0 + seg * 8;
            cpa16(sb + (PV_V(0, hl) + (uint32_t)(row * 40 + seg * 8)) * 2, src);
        }
        CP_COMMIT();
    }
    // prefetch S chunk 0 into regs
    float sreg[16];
    {
        const float* sp = Sr + half * 16;
        *(float4*)(sreg)      = *(const float4*)(sp);
        *(float4*)(sreg + 4)  = *(const float4*)(sp + 4);
        *(float4*)(sreg + 8)  = *(const float4*)(sp + 8);
        *(float4*)(sreg + 12) = *(const float4*)(sp + 12);
    }

    for (int it = 0; it < 64; it++) {
        const int kt = it * 32;
        const int pb = it & 1;
        // consume sreg: exp-normalize, write back to S, split, STS P
        {
            uint4 hi, lo;
            #pragma unroll
            for (int s = 0; s < 2; s++) {
                float v[8];
                #pragma unroll
                for (int j = 0; j < 8; j++)
                    v[j] = __expf(sreg[s * 8 + j] - st.x) * st.y;
                float* sp = Sr + kt + half * 16 + s * 8;
                *(float4*)(sp)     = make_float4(v[0], v[1], v[2], v[3]);
                *(float4*)(sp + 4) = make_float4(v[4], v[5], v[6], v[7]);
                split8(v, hi, lo);
                const uint32_t off = (uint32_t)(r * 40 + half * 16 + s * 8) * 2;
                *(uint4*)((char*)sm + (PV_P(pb, 0)) * 2 + off) = hi;
                *(uint4*)((char*)sm + (PV_P(pb, 1)) * 2 + off) = lo;
            }
        }
        // prefetch S chunk it+1 into regs (latency hidden behind MMA)
        if (it + 1 < 64) {
            const float* sp = Sr + (it + 1) * 32 + half * 16;
            *(float4*)(sreg)      = *(const float4*)(sp);
            *(float4*)(sreg + 4)  = *(const float4*)(sp + 4);
            *(float4*)(sreg + 8)  = *(const float4*)(sp + 8);
            *(float4*)(sreg + 12) = *(const float4*)(sp + 12);
        }
        // prefetch V chunk it+1
        if (it + 1 < 64) {
            const int vb = (it + 1) & 1;
            const int kn = (it + 1) * 32;
            #pragma unroll
            for (int c = 0; c < 2; c++) {
                const int id = c * 256 + t;
                const int hl = id >> 8;
                const int row = (id >> 2) & 63;
                const int seg = id & 3;
                const __nv_bfloat16* src =
                    (hl ? Vl0 : Vh0) + (size_t)row * 2048 + kn + seg * 8;
                cpa16(sb + (PV_V(vb, hl) + (uint32_t)(row * 40 + seg * 8)) * 2, src);
            }
            CP_COMMIT();
            CP_WAIT1();
        } else {
            CP_WAIT0();
        }
        __syncthreads();

        const uint32_t ph = sb + PV_P(pb, 0) * 2, pl = sb + PV_P(pb, 1) * 2;
        const uint32_t vh = sb + PV_V(pb, 0) * 2, vl = sb + PV_V(pb, 1) * 2;
        #pragma unroll
        for (int k16 = 0; k16 < 2; k16++) {
            const int k0 = k16 * 16;
            uint32_t afh[2][4], afl[2][4], bfh[2][4], bfl[2][4];
            #pragma unroll
            for (int mi = 0; mi < 2; mi++) {
                ldsm4(afh[mi], fa40(ph, wm * 32 + mi * 16, k0, lane));
                ldsm4(afl[mi], fa40(pl, wm * 32 + mi * 16, k0, lane));
            }
            #pragma unroll
            for (int ng = 0; ng < 2; ng++) {
                ldsm4(bfh[ng], fa40(vh, wn * 32 + ng * 16, k0, lane));
                ldsm4(bfl[ng], fa40(vl, wn * 32 + ng * 16, k0, lane));
            }
            #pragma unroll
            for (int mi = 0; mi < 2; mi++)
                #pragma unroll
                for (int nj = 0; nj < 4; nj++) {
                    const int ng = nj >> 1, hh = nj & 1;
                    mma16816(acc[mi][nj], afh[mi], bfh[ng][hh], bfh[ng][hh + 2]);
                    mma16816(acc[mi][nj], afh[mi], bfl[ng][hh], bfl[ng][hh + 2]);
                    mma16816(acc[mi][nj], afl[mi], bfh[ng][hh], bfh[ng][hh + 2]);
                }
        }
        __syncthreads();
    }

    const int bb = z >> 4, h = z & 15;
    #pragma unroll
    for (int mi = 0; mi < 2; mi++)
        #pragma unroll
        for (int nj = 0; nj < 4; nj++) {
            const int r0 = bm + wm * 32 + mi * 16 + (lane >> 2);
            const int c  = wn * 32 + nj * 8 + (lane & 3) * 2;
            #pragma unroll
            for (int hf = 0; hf < 2; hf++) {
                const int rr = r0 + hf * 8;
                *(float2*)&g_Oh[((size_t)bb * LQ_ + rr) * HDA + h * 64 + c] =
                    make_float2(acc[mi][nj][hf * 2], acc[mi][nj][hf * 2 + 1]);
            }
        }
}

// ---------------------------------------------------------------------------
// Output GEMM: out = Oh @ wo^T + bo. (unchanged)
// ---------------------------------------------------------------------------
__global__ __launch_bounds__(256) void o_kernel(
    const float* __restrict__ wo, const float* __restrict__ bo,
    float* __restrict__ out)
{
    const int bm = blockIdx.x * 64;
    __shared__ float As[16][68];
    __shared__ float Ws[16][68];
    const int t  = threadIdx.x;
    const int tx = t % 16, ty = t / 16;
    const int lk = t % 16, lr = t / 16;

    u64 acc2[4][2];
    #pragma unroll
    for (int i = 0; i < 4; i++) {
        acc2[i][0] = pack2(0.f, 0.f);
        acc2[i][1] = pack2(0.f, 0.f);
    }

    for (int kt = 0; kt < HDA; kt += 16) {
        #pragma unroll
        for (int i = 0; i < 4; i++) {
            const int m = i * 16 + lr;
            As[lk][m] = g_Oh[(size_t)(bm + m) * HDA + kt + lk];
            Ws[lk][m] = wo  [(size_t)m        * HDA + kt + lk];
        }
        __syncthreads();
        #pragma unroll
        for (int kk = 0; kk < 16; kk++) {
            float a[4], b[4];
            #pragma unroll
            for (int i = 0; i < 4; i++) a[i] = As[kk][ty * 4 + i];
            #pragma unroll
            for (int j = 0; j < 4; j++) b[j] = Ws[kk][tx + 16 * j];
            const u64 b20 = pack2(b[0], b[1]);
            const u64 b21 = pack2(b[2], b[3]);
            #pragma unroll
            for (int i = 0; i < 4; i++) {
                const u64 a2 = pack2(a[i], a[i]);
                acc2[i][0] = ffma2(a2, b20, acc2[i][0]);
                acc2[i][1] = ffma2(a2, b21, acc2[i][1]);
            }
        }
        __syncthreads();
    }

    #pragma unroll
    for (int i = 0; i < 4; i++) {
        const int m = bm + ty * 4 + i;
        float2 p0 = unpack2(acc2[i][0]), p1 = unpack2(acc2[i][1]);
        out[(size_t)m * HD_ + tx]      = p0.x + bo[tx];
        out[(size_t)m * HD_ + tx + 16] = p0.y + bo[tx + 16];
        out[(size_t)m * HD_ + tx + 32] = p1.x + bo[tx + 32];
        out[(size_t)m * HD_ + tx + 48] = p1.y + bo[tx + 48];
    }
}

// ---------------------------------------------------------------------------
extern "C" void kernel_launch(void* const* d_in, const int* in_sizes, int n_in,
                              void* d_out, int out_size)
{
    (void)in_sizes; (void)n_in; (void)out_size;
    const float* q    = (const float*)d_in[0];
    const float* k    = (const float*)d_in[1];
    const float* v    = (const float*)d_in[2];
    const int*   mask = (const int*)  d_in[3];
    const float* wq   = (const float*)d_in[4];
    const float* bq   = (const float*)d_in[5];
    const float* wk   = (const float*)d_in[6];
    const float* bk   = (const float*)d_in[7];
    const float* wv   = (const float*)d_in[8];
    const float* bv   = (const float*)d_in[9];
    const float* wo   = (const float*)d_in[10];
    const float* bo   = (const float*)d_in[11];

    float* out    = (float*)d_out;                       // [B, LQ, 64]
    float* scores = out + (size_t)B_ * LQ_ * HD_;        // [B, H, LQ, LK]

    __nv_bfloat16 *Xhi, *Xlo, *Whi, *Wlo, *Qhi, *Qlo, *Khi, *Klo;
    float* Vf;
    cudaGetSymbolAddress((void**)&Xhi, g_Xhi);
    cudaGetSymbolAddress((void**)&Xlo, g_Xlo);
    cudaGetSymbolAddress((void**)&Whi, g_Whi);
    cudaGetSymbolAddress((void**)&Wlo, g_Wlo);
    cudaGetSymbolAddress((void**)&Qhi, g_Qhi);
    cudaGetSymbolAddress((void**)&Qlo, g_Qlo);
    cudaGetSymbolAddress((void**)&Khi, g_Khi);
    cudaGetSymbolAddress((void**)&Klo, g_Klo);
    cudaGetSymbolAddress((void**)&Vf,  g_Vf);

    const int QK_SMEM = 4 * 128 * 72 * 2;                // 73728 B
    cudaFuncSetAttribute(qk_mma, cudaFuncAttributeMaxDynamicSharedMemorySize,
                         QK_SMEM);
    cudaFuncSetAttribute(pv_mma, cudaFuncAttributeMaxDynamicSharedMemorySize,
                         PV_SMEM);
    cudaFuncSetAttribute(proj_mma, cudaFuncAttributeMaxDynamicSharedMemorySize,
                         PJ_SMEM);

    const dim3 blk(256);
    const int  NX8 = (B_ * LQ_ * IND) / 8;               // 1048576
    const int  NW8 = (IND * IND) / 8;                    // 131072
    const dim3 gproj(IND / 128, (B_ * LQ_) / 128);       // (8, 64)

    // Q projection
    split_kernel<<<NX8 / 256, blk>>>(q, Xhi, Xlo, NX8);
    split_kernel<<<NW8 / 256, blk>>>(wq, Whi, Wlo, NW8);
    proj_mma<<<gproj, 512, PJ_SMEM>>>(bq, 0.125f, 1, nullptr, Qhi, Qlo);
    // K projection
    split_kernel<<<NX8 / 256, blk>>>(k, Xhi, Xlo, NX8);
    split_kernel<<<NW8 / 256, blk>>>(wk, Whi, Wlo, NW8);
    proj_mma<<<gproj, 512, PJ_SMEM>>>(bk, 1.0f, 1, nullptr, Khi, Klo);
    // V projection
    split_kernel<<<NX8 / 256, blk>>>(v, Xhi, Xlo, NX8);
    split_kernel<<<NW8 / 256, blk>>>(wv, Whi, Wlo, NW8);
    proj_mma<<<gproj, 512, PJ_SMEM>>>(bv, 1.0f, 0, Vf, nullptr, nullptr);

    vtrans_kernel<<<dim3(LK_ / 64, NZ), blk>>>();        // (32, 64)

    qk_mma<<<dim3(LK_ / 128, LQ_ / 128, NZ), 512, QK_SMEM>>>(mask, scores);

    combine_kernel<<<(NZ * LQ_ + 255) / 256, blk>>>();   // 512 blocks

    pv_mma<<<dim3(LQ_ / 128, NZ), blk, PV_SMEM>>>(scores);

    o_kernel<<<(B_ * LQ_) / 64, blk>>>(wo, bo, out);     // 128 blocks
}